// round 11
// baseline (speedup 1.0000x reference)
#include <cuda_runtime.h>

// Math replicates XLA:CPU cephes/Eigen lowering bit-for-bit (validated R5-R10).
// f32x2 packed ops do two independent IEEE-rn f32 ops -> bitwise identical per
// half. rcp.rn(x) == div.rn(1,x) bitwise (both correctly rounded, validated R10).
// Params stay in shuffle-broadcast registers — smem float4 path regressed (R10).

#define FULLMASK 0xFFFFFFFFu
#define NWARPS 8
#define KMIX 10
#define HW 1024
#define LOG127_5 4.8481163645984802f

typedef unsigned long long ull;

__device__ __forceinline__ ull pk2(float a, float b) {
    ull r; asm("mov.b64 %0,{%1,%2};" : "=l"(r) : "f"(a), "f"(b)); return r;
}
__device__ __forceinline__ void up2(ull p, float& a, float& b) {
    asm("mov.b64 {%0,%1},%2;" : "=f"(a), "=f"(b) : "l"(p));
}
__device__ __forceinline__ ull mul2(ull a, ull b) {
    ull r; asm("mul.rn.f32x2 %0,%1,%2;" : "=l"(r) : "l"(a), "l"(b)); return r;
}
__device__ __forceinline__ ull add2(ull a, ull b) {
    ull r; asm("add.rn.f32x2 %0,%1,%2;" : "=l"(r) : "l"(a), "l"(b)); return r;
}
__device__ __forceinline__ ull fma2(ull a, ull b, ull c) {
    ull r; asm("fma.rn.f32x2 %0,%1,%2,%3;" : "=l"(r) : "l"(a), "l"(b), "l"(c)); return r;
}
__device__ __forceinline__ ull neg2(ull a) { return a ^ 0x8000000080000000ull; }
__device__ __forceinline__ float rcp_rn(float x) {
    float r; asm("rcp.rn.f32 %0,%1;" : "=f"(r) : "f"(x)); return r;
}

// ---- scalar cephes exp/log (reference-bit-exact) ----
__device__ __forceinline__ float xla_exp(float x) {
    x = fminf(fmaxf(x, -88.3762626647949f), 88.3762626647950f);
    float fx = floorf(__fmaf_rn(x, 1.44269504088896341f, 0.5f));
    float r = __fsub_rn(x, __fmul_rn(fx, 0.693359375f));
    r = __fsub_rn(r, __fmul_rn(fx, -2.12194440e-4f));
    float z = __fmul_rn(r, r);
    float y = 1.9875691500E-4f;
    y = __fmaf_rn(y, r, 1.3981999507E-3f);
    y = __fmaf_rn(y, r, 8.3334519073E-3f);
    y = __fmaf_rn(y, r, 4.1665795894E-2f);
    y = __fmaf_rn(y, r, 1.6666665459E-1f);
    y = __fmaf_rn(y, r, 5.0000001201E-1f);
    y = __fmaf_rn(y, z, r);
    y = __fadd_rn(y, 1.0f);
    int n = (int)fx;
    return __fmul_rn(y, __int_as_float((n + 127) << 23));
}

__device__ __forceinline__ float xla_log(float x) {
    int bits = __float_as_int(x);
    float e = (float)((bits >> 23) - 126);
    float m = __int_as_float((bits & 0x007fffff) | 0x3f000000);
    if (m < 0.707106781186547524f) {
        e = __fsub_rn(e, 1.0f);
        m = __fadd_rn(__fsub_rn(m, 1.0f), m);
    } else {
        m = __fsub_rn(m, 1.0f);
    }
    float z = __fmul_rn(m, m);
    float y = 7.0376836292E-2f;
    y = __fmaf_rn(y, m, -1.1514610310E-1f);
    y = __fmaf_rn(y, m, 1.1676998740E-1f);
    y = __fmaf_rn(y, m, -1.2420140846E-1f);
    y = __fmaf_rn(y, m, 1.4249322787E-1f);
    y = __fmaf_rn(y, m, -1.6668057665E-1f);
    y = __fmaf_rn(y, m, 2.0000714765E-1f);
    y = __fmaf_rn(y, m, -2.4999993993E-1f);
    y = __fmaf_rn(y, m, 3.3333331174E-1f);
    y = __fmul_rn(y, m);
    y = __fmul_rn(y, z);
    y = __fadd_rn(y, __fmul_rn(e, -2.12194440e-4f));
    y = __fsub_rn(y, __fmul_rn(z, 0.5f));
    float res = __fadd_rn(m, y);
    res = __fadd_rn(res, __fmul_rn(e, 0.693359375f));
    return res;
}

// ---- packed-pair exp/log: bitwise identical per half to scalar versions ----
__device__ __forceinline__ void xla_exp2(float xa, float xb, float& ra, float& rb) {
    xa = fminf(fmaxf(xa, -88.3762626647949f), 88.3762626647950f);
    xb = fminf(fmaxf(xb, -88.3762626647949f), 88.3762626647950f);
    ull x2 = pk2(xa, xb);
    ull fx2 = fma2(x2, pk2(1.44269504088896341f, 1.44269504088896341f),
                   pk2(0.5f, 0.5f));
    float fa, fb; up2(fx2, fa, fb);
    fa = floorf(fa); fb = floorf(fb);
    fx2 = pk2(fa, fb);
    ull r2 = add2(x2, neg2(mul2(fx2, pk2(0.693359375f, 0.693359375f))));
    r2 = add2(r2, neg2(mul2(fx2, pk2(-2.12194440e-4f, -2.12194440e-4f))));
    ull z2 = mul2(r2, r2);
    ull y2 = pk2(1.9875691500E-4f, 1.9875691500E-4f);
    y2 = fma2(y2, r2, pk2(1.3981999507E-3f, 1.3981999507E-3f));
    y2 = fma2(y2, r2, pk2(8.3334519073E-3f, 8.3334519073E-3f));
    y2 = fma2(y2, r2, pk2(4.1665795894E-2f, 4.1665795894E-2f));
    y2 = fma2(y2, r2, pk2(1.6666665459E-1f, 1.6666665459E-1f));
    y2 = fma2(y2, r2, pk2(5.0000001201E-1f, 5.0000001201E-1f));
    y2 = fma2(y2, z2, r2);
    y2 = add2(y2, pk2(1.0f, 1.0f));
    float ya, yb; up2(y2, ya, yb);
    int na = (int)fa, nb = (int)fb;
    ra = __fmul_rn(ya, __int_as_float((na + 127) << 23));
    rb = __fmul_rn(yb, __int_as_float((nb + 127) << 23));
}

__device__ __forceinline__ void xla_log2(float xa, float xb, float& ra, float& rb) {
    int ba = __float_as_int(xa), bb = __float_as_int(xb);
    float ea = (float)((ba >> 23) - 126);
    float eb = (float)((bb >> 23) - 126);
    float ma = __int_as_float((ba & 0x007fffff) | 0x3f000000);
    float mb = __int_as_float((bb & 0x007fffff) | 0x3f000000);
    if (ma < 0.707106781186547524f) {
        ea = __fsub_rn(ea, 1.0f);
        ma = __fadd_rn(__fsub_rn(ma, 1.0f), ma);
    } else {
        ma = __fsub_rn(ma, 1.0f);
    }
    if (mb < 0.707106781186547524f) {
        eb = __fsub_rn(eb, 1.0f);
        mb = __fadd_rn(__fsub_rn(mb, 1.0f), mb);
    } else {
        mb = __fsub_rn(mb, 1.0f);
    }
    ull m2 = pk2(ma, mb);
    ull z2 = mul2(m2, m2);
    ull y2 = pk2(7.0376836292E-2f, 7.0376836292E-2f);
    y2 = fma2(y2, m2, pk2(-1.1514610310E-1f, -1.1514610310E-1f));
    y2 = fma2(y2, m2, pk2(1.1676998740E-1f, 1.1676998740E-1f));
    y2 = fma2(y2, m2, pk2(-1.2420140846E-1f, -1.2420140846E-1f));
    y2 = fma2(y2, m2, pk2(1.4249322787E-1f, 1.4249322787E-1f));
    y2 = fma2(y2, m2, pk2(-1.6668057665E-1f, -1.6668057665E-1f));
    y2 = fma2(y2, m2, pk2(2.0000714765E-1f, 2.0000714765E-1f));
    y2 = fma2(y2, m2, pk2(-2.4999993993E-1f, -2.4999993993E-1f));
    y2 = fma2(y2, m2, pk2(3.3333331174E-1f, 3.3333331174E-1f));
    y2 = mul2(y2, m2);
    y2 = mul2(y2, z2);
    ull e2 = pk2(ea, eb);
    y2 = add2(y2, mul2(e2, pk2(-2.12194440e-4f, -2.12194440e-4f)));
    y2 = add2(y2, neg2(mul2(z2, pk2(0.5f, 0.5f))));
    ull res2 = add2(m2, y2);
    res2 = add2(res2, mul2(e2, pk2(0.693359375f, 0.693359375f)));
    up2(res2, ra, rb);
}

__device__ __forceinline__ float xla_log1p(float x) {
    float u = __fadd_rn(x, 1.0f);
    float w = __fmul_rn(xla_log(u), __fdiv_rn(x, __fsub_rn(u, 1.0f)));
    return (u == 1.0f) ? x : w;
}

__device__ __forceinline__ float xla_tanh(float x) {
    float xc = fminf(fmaxf(x, -7.90531110763549805f), 7.90531110763549805f);
    float x2 = __fmul_rn(xc, xc);
    float p = -2.76076847742355e-16f;
    p = __fmaf_rn(p, x2, 2.00018790482477e-13f);
    p = __fmaf_rn(p, x2, -8.60467152213735e-11f);
    p = __fmaf_rn(p, x2, 5.12229709037114e-08f);
    p = __fmaf_rn(p, x2, 1.48572235717979e-05f);
    p = __fmaf_rn(p, x2, 6.37261928875436e-04f);
    p = __fmaf_rn(p, x2, 4.89352455891786e-03f);
    float num = __fmul_rn(xc, p);
    float q = 1.19825839466702e-06f;
    q = __fmaf_rn(q, x2, 1.18534705686654e-04f);
    q = __fmaf_rn(q, x2, 2.26843463243900e-03f);
    q = __fmaf_rn(q, x2, 4.89352518554385e-03f);
    float r = __fdiv_rn(num, q);
    return (fabsf(x) < 0.0004f) ? x : r;
}

__device__ __forceinline__ float xla_sigmoid(float x) {
    return rcp_rn(__fadd_rn(1.0f, xla_exp(-x)));   // == div.rn(1, .) bitwise
}

__device__ __forceinline__ float xla_softplus(float x) {
    return __fadd_rn(fmaxf(x, 0.0f), xla_log1p(xla_exp(-fabsf(x))));
}

// extra-bin logprob: interior case packs its two boundary sigmoids into one exp2
__device__ __forceinline__ float bin_logprob_ex(int t, float m, float iv, float s) {
    if (t == 0) {
        float n0 = __fmul_rn(__fsub_rn(-0.9921875f, m), iv);
        return __fsub_rn(n0, xla_softplus(n0));
    }
    if (t == 255) {
        float n = __fmul_rn(__fsub_rn(0.9921875f, m), iv);
        return -xla_softplus(n);
    }
    float clo = __fadd_rn(__fmul_rn((float)t, 0.0078125f), -1.0f);
    float chi = __fadd_rn(__fmul_rn((float)(t + 1), 0.0078125f), -1.0f);
    float zhi = __fmul_rn(__fsub_rn(chi, m), iv);
    float zlo = __fmul_rn(__fsub_rn(clo, m), iv);
    float ehi, elo;
    xla_exp2(-zhi, -zlo, ehi, elo);
    float shi = rcp_rn(__fadd_rn(1.0f, ehi));
    float slo = rcp_rn(__fadd_rn(1.0f, elo));
    float pdf = __fsub_rn(shi, slo);
    if (pdf > 1e-5f) {
        return xla_log(fmaxf(pdf, 1e-12f));
    }
    float midc = __fadd_rn(__fmul_rn((float)(2 * t + 1), 0.00390625f), -1.0f);
    float mid = __fmul_rn(__fsub_rn(midc, m), iv);
    float mlp = __fsub_rn(__fsub_rn(mid, s), __fmul_rn(2.0f, xla_softplus(mid)));
    return __fsub_rn(mlp, LOG127_5);
}

__global__ __launch_bounds__(32 * NWARPS)
void mixlogistic_decode_kernel(const float* __restrict__ x,
                               const float* __restrict__ l,
                               const int* __restrict__ epsp,
                               float* __restrict__ out,
                               int npix)
{
    __shared__ float sLOG[NWARPS][KMIX];
    __shared__ float sLPI[NWARPS][KMIX];
    __shared__ float sM  [NWARPS][3][KMIX];
    __shared__ float sS  [NWARPS][3][KMIX];
    __shared__ float sINV[NWARPS][3][KMIX];
    __shared__ float sCF [NWARPS][3][KMIX];

    const int warp = threadIdx.x >> 5;
    const int lane = threadIdx.x & 31;
    const int P = blockIdx.x * NWARPS + warp;
    if (P >= npix) return;

    const int b  = P >> 10;
    const int hw = P & (HW - 1);

    for (int c = lane; c < 100; c += 32) {
        float v = l[(size_t)(b * 100 + c) * HW + hw];
        if (c < KMIX) {
            sLOG[warp][c] = v;
        } else {
            int cc  = (c - KMIX) / 30;
            int rem = (c - KMIX) % 30;
            int grp = rem / KMIX;
            int k   = rem % KMIX;
            if (grp == 0) {
                sM[warp][cc][k] = v;
            } else if (grp == 1) {
                float s = fmaxf(v, -7.0f);
                sS[warp][cc][k]   = s;
                sINV[warp][cc][k] = xla_exp(-s);
            } else {
                sCF[warp][cc][k] = xla_tanh(v);
            }
        }
    }
    __syncwarp();

    // cooperative log_softmax (exact fmax butterfly + parallel exp +
    // sequential ascending-k fold == XLA reduce rounding)
    {
        float lg = (lane < KMIX) ? sLOG[warp][lane] : -INFINITY;
        float mx = lg;
        #pragma unroll
        for (int off = 16; off; off >>= 1)
            mx = fmaxf(mx, __shfl_xor_sync(FULLMASK, mx, off));
        float e = xla_exp(__fsub_rn(lg, mx));
        float sum = 0.0f;
        #pragma unroll
        for (int k = 0; k < KMIX; k++)
            sum = __fadd_rn(sum, __shfl_sync(FULLMASK, e, k));
        float lsum = xla_log(sum);
        if (lane < KMIX)
            sLPI[warp][lane] = __fsub_rn(__fsub_rn(lg, mx), lsum);
    }
    __syncwarp();

    const int eps = epsp[0];
    float xr = 0.0f, xg = 0.0f;

    #pragma unroll
    for (int c = 0; c < 3; c++) {
        float xorig = x[(size_t)(b * 3 + c) * HW + hw];
        int r  = (int)(__fadd_rn(__fmul_rn(xorig, 127.5f), 127.5f));
        int lb = max(r - eps, 0);
        int ub = min(r + eps, 255);

        const int t0 = lb + lane;
        const bool v0 = (t0 <= ub);
        const float chi = __fadd_rn(__fmul_rn((float)(t0 + 1), 0.0078125f), -1.0f);

        // per-component params in lanes 0..9
        float mk = 0.0f, ivk = 0.0f, sk = 0.0f, lpik = 0.0f;
        if (lane < KMIX) {
            mk = sM[warp][c][lane];
            if (c == 1) {
                mk = __fadd_rn(mk, __fmul_rn(sCF[warp][0][lane], xr));
            } else if (c == 2) {
                mk = __fadd_rn(mk, __fmul_rn(sCF[warp][1][lane], xr));
                mk = __fadd_rn(mk, __fmul_rn(sCF[warp][2][lane], xg));
            }
            ivk  = sINV[warp][c][lane];
            sk   = sS[warp][c][lane];
            lpik = sLPI[warp][lane];
        }

        // lane-0 lower-boundary sigmoid per component (iff lb >= 1)
        float E = 0.0f;
        if (lb >= 1) {
            float cloLB = __fadd_rn(__fmul_rn((float)lb, 0.0078125f), -1.0f);
            E = xla_sigmoid(__fmul_rn(__fsub_rn(cloLB, mk), ivk));
        }

        // cooperative 33rd bin
        const int te = lb + 32;
        const bool haveExtra = (te <= ub);
        float lpe = -INFINITY;
        if (haveExtra && lane < KMIX) {
            lpe = __fadd_rn(bin_logprob_ex(te, mk, ivk, sk), lpik);
        }

        // ---- main 32 bins: components processed in packed pairs ----
        float lp0[KMIX];
        #pragma unroll
        for (int j = 0; j < KMIX / 2; j++) {
            const int k0 = 2 * j, k1 = 2 * j + 1;
            float m0   = __shfl_sync(FULLMASK, mk,   k0);
            float m1   = __shfl_sync(FULLMASK, mk,   k1);
            float iv0  = __shfl_sync(FULLMASK, ivk,  k0);
            float iv1  = __shfl_sync(FULLMASK, ivk,  k1);
            float s0   = __shfl_sync(FULLMASK, sk,   k0);
            float s1   = __shfl_sync(FULLMASK, sk,   k1);
            float lpi0 = __shfl_sync(FULLMASK, lpik, k0);
            float lpi1 = __shfl_sync(FULLMASK, lpik, k1);
            float E0   = __shfl_sync(FULLMASK, E,    k0);
            float E1   = __shfl_sync(FULLMASK, E,    k1);

            float zhi0 = __fmul_rn(__fsub_rn(chi, m0), iv0);
            float zhi1 = __fmul_rn(__fsub_rn(chi, m1), iv1);
            float e0, e1;
            xla_exp2(-zhi0, -zhi1, e0, e1);
            float S0 = rcp_rn(__fadd_rn(1.0f, e0));
            float S1 = rcp_rn(__fadd_rn(1.0f, e1));
            float slo0 = __shfl_up_sync(FULLMASK, S0, 1);
            float slo1 = __shfl_up_sync(FULLMASK, S1, 1);
            if (lane == 0) { slo0 = E0; slo1 = E1; }

            float pdf0 = __fsub_rn(S0, slo0);
            float pdf1 = __fsub_rn(S1, slo1);
            float lg0, lg1;
            xla_log2(fmaxf(pdf0, 1e-12f), fmaxf(pdf1, 1e-12f), lg0, lg1);

            float lpA, lpB;
            if (t0 == 0) {
                lpA = __fsub_rn(zhi0, xla_softplus(zhi0));
                lpB = __fsub_rn(zhi1, xla_softplus(zhi1));
            } else if (t0 == 255) {
                float zloA = __fmul_rn(__fsub_rn(0.9921875f, m0), iv0);
                float zloB = __fmul_rn(__fsub_rn(0.9921875f, m1), iv1);
                lpA = -xla_softplus(zloA);
                lpB = -xla_softplus(zloB);
            } else {
                if (pdf0 > 1e-5f) {
                    lpA = lg0;
                } else {
                    float midc = __fadd_rn(__fmul_rn((float)(2 * t0 + 1), 0.00390625f), -1.0f);
                    float mid  = __fmul_rn(__fsub_rn(midc, m0), iv0);
                    lpA = __fsub_rn(__fsub_rn(__fsub_rn(mid, s0),
                                              __fmul_rn(2.0f, xla_softplus(mid))), LOG127_5);
                }
                if (pdf1 > 1e-5f) {
                    lpB = lg1;
                } else {
                    float midc = __fadd_rn(__fmul_rn((float)(2 * t0 + 1), 0.00390625f), -1.0f);
                    float mid  = __fmul_rn(__fsub_rn(midc, m1), iv1);
                    lpB = __fsub_rn(__fsub_rn(__fsub_rn(mid, s1),
                                              __fmul_rn(2.0f, xla_softplus(mid))), LOG127_5);
                }
            }
            lp0[k0] = __fadd_rn(lpA, lpi0);
            lp0[k1] = __fadd_rn(lpB, lpi1);
        }

        // per-bin logsumexp over k (sequential ascending k; packed sub + exps)
        float bv = -INFINITY;
        int   bt = 0x7FFFFFFF;
        if (v0) {
            float amax = lp0[0];
            #pragma unroll
            for (int k = 1; k < KMIX; k++) amax = fmaxf(amax, lp0[k]);
            ull am2 = pk2(amax, amax);
            float ex[KMIX];
            #pragma unroll
            for (int j = 0; j < KMIX / 2; j++) {
                float da, db;
                up2(add2(pk2(lp0[2 * j], lp0[2 * j + 1]), neg2(am2)), da, db);
                xla_exp2(da, db, ex[2 * j], ex[2 * j + 1]);
            }
            float sum = 0.0f;
            #pragma unroll
            for (int k = 0; k < KMIX; k++) sum = __fadd_rn(sum, ex[k]);
            bv = __fadd_rn(xla_log(sum), amax);
            bt = t0;
        }

        // warp argmax (first-index tie semantics)
        #pragma unroll
        for (int off = 16; off; off >>= 1) {
            float ov = __shfl_down_sync(FULLMASK, bv, off);
            int   ot = __shfl_down_sync(FULLMASK, bt, off);
            if (ov > bv || (ov == bv && ot < bt)) { bv = ov; bt = ot; }
        }

        // extra-bin logsumexp (uniform result; final compare on lane 0)
        if (haveExtra) {
            float amax = lpe;
            #pragma unroll
            for (int off = 16; off; off >>= 1)
                amax = fmaxf(amax, __shfl_xor_sync(FULLMASK, amax, off));
            float e = xla_exp(__fsub_rn(lpe, amax));
            float sum = 0.0f;
            #pragma unroll
            for (int k = 0; k < KMIX; k++)
                sum = __fadd_rn(sum, __shfl_sync(FULLMASK, e, k));
            float val = __fadd_rn(xla_log(sum), amax);
            if (lane == 0 && val > bv) { bv = val; bt = te; }
        }

        bt = __shfl_sync(FULLMASK, bt, 0);

        float outv = __fdiv_rn(__fsub_rn((float)bt, 127.5f), 127.5f);
        if (c == 0) xr = outv;
        else if (c == 1) xg = outv;

        if (lane == 0) {
            out[(size_t)(b * 3 + c) * HW + hw] = outv;
        }
    }
}

extern "C" void kernel_launch(void* const* d_in, const int* in_sizes, int n_in,
                              void* d_out, int out_size)
{
    const float* x   = (const float*)d_in[0];
    const float* l   = (const float*)d_in[1];
    const int*   eps = (const int*)d_in[2];
    float* out = (float*)d_out;

    int npix = in_sizes[0] / 3;
    int blocks = (npix + NWARPS - 1) / NWARPS;
    mixlogistic_decode_kernel<<<blocks, 32 * NWARPS>>>(x, l, eps, out, npix);
}

// round 12
// speedup vs baseline: 1.1168x; 1.1168x over previous
#include <cuda_runtime.h>

// Math replicates XLA:CPU cephes/Eigen lowering bit-for-bit (validated R5-R11).
// f32x2 packed ops do two independent IEEE-rn f32 ops -> bitwise identical per
// half. rcp.rn(x) == div.rn(1,x) bitwise (validated R10/R11).
// Params via shuffle-broadcast (smem float4 path regressed, R10).

#define FULLMASK 0xFFFFFFFFu
#define NWARPS 8
#define KMIX 10
#define HW 1024
#define LOG127_5 4.8481163645984802f

typedef unsigned long long ull;

__device__ __forceinline__ ull pk2(float a, float b) {
    ull r; asm("mov.b64 %0,{%1,%2};" : "=l"(r) : "f"(a), "f"(b)); return r;
}
__device__ __forceinline__ void up2(ull p, float& a, float& b) {
    asm("mov.b64 {%0,%1},%2;" : "=f"(a), "=f"(b) : "l"(p));
}
__device__ __forceinline__ ull mul2(ull a, ull b) {
    ull r; asm("mul.rn.f32x2 %0,%1,%2;" : "=l"(r) : "l"(a), "l"(b)); return r;
}
__device__ __forceinline__ ull add2(ull a, ull b) {
    ull r; asm("add.rn.f32x2 %0,%1,%2;" : "=l"(r) : "l"(a), "l"(b)); return r;
}
__device__ __forceinline__ ull fma2(ull a, ull b, ull c) {
    ull r; asm("fma.rn.f32x2 %0,%1,%2,%3;" : "=l"(r) : "l"(a), "l"(b), "l"(c)); return r;
}
__device__ __forceinline__ ull neg2(ull a) { return a ^ 0x8000000080000000ull; }
__device__ __forceinline__ float rcp_rn(float x) {
    float r; asm("rcp.rn.f32 %0,%1;" : "=f"(r) : "f"(x)); return r;
}

// ---- scalar cephes exp/log (reference-bit-exact) ----
__device__ __forceinline__ float xla_exp(float x) {
    x = fminf(fmaxf(x, -88.3762626647949f), 88.3762626647950f);
    float fx = floorf(__fmaf_rn(x, 1.44269504088896341f, 0.5f));
    float r = __fsub_rn(x, __fmul_rn(fx, 0.693359375f));
    r = __fsub_rn(r, __fmul_rn(fx, -2.12194440e-4f));
    float z = __fmul_rn(r, r);
    float y = 1.9875691500E-4f;
    y = __fmaf_rn(y, r, 1.3981999507E-3f);
    y = __fmaf_rn(y, r, 8.3334519073E-3f);
    y = __fmaf_rn(y, r, 4.1665795894E-2f);
    y = __fmaf_rn(y, r, 1.6666665459E-1f);
    y = __fmaf_rn(y, r, 5.0000001201E-1f);
    y = __fmaf_rn(y, z, r);
    y = __fadd_rn(y, 1.0f);
    int n = (int)fx;
    return __fmul_rn(y, __int_as_float((n + 127) << 23));
}

__device__ __forceinline__ float xla_log(float x) {
    int bits = __float_as_int(x);
    float e = (float)((bits >> 23) - 126);
    float m = __int_as_float((bits & 0x007fffff) | 0x3f000000);
    if (m < 0.707106781186547524f) {
        e = __fsub_rn(e, 1.0f);
        m = __fadd_rn(__fsub_rn(m, 1.0f), m);
    } else {
        m = __fsub_rn(m, 1.0f);
    }
    float z = __fmul_rn(m, m);
    float y = 7.0376836292E-2f;
    y = __fmaf_rn(y, m, -1.1514610310E-1f);
    y = __fmaf_rn(y, m, 1.1676998740E-1f);
    y = __fmaf_rn(y, m, -1.2420140846E-1f);
    y = __fmaf_rn(y, m, 1.4249322787E-1f);
    y = __fmaf_rn(y, m, -1.6668057665E-1f);
    y = __fmaf_rn(y, m, 2.0000714765E-1f);
    y = __fmaf_rn(y, m, -2.4999993993E-1f);
    y = __fmaf_rn(y, m, 3.3333331174E-1f);
    y = __fmul_rn(y, m);
    y = __fmul_rn(y, z);
    y = __fadd_rn(y, __fmul_rn(e, -2.12194440e-4f));
    y = __fsub_rn(y, __fmul_rn(z, 0.5f));
    float res = __fadd_rn(m, y);
    res = __fadd_rn(res, __fmul_rn(e, 0.693359375f));
    return res;
}

// ---- packed-pair exp/log: bitwise identical per half to scalar versions ----
__device__ __forceinline__ void xla_exp2(float xa, float xb, float& ra, float& rb) {
    xa = fminf(fmaxf(xa, -88.3762626647949f), 88.3762626647950f);
    xb = fminf(fmaxf(xb, -88.3762626647949f), 88.3762626647950f);
    ull x2 = pk2(xa, xb);
    ull fx2 = fma2(x2, pk2(1.44269504088896341f, 1.44269504088896341f),
                   pk2(0.5f, 0.5f));
    float fa, fb; up2(fx2, fa, fb);
    fa = floorf(fa); fb = floorf(fb);
    fx2 = pk2(fa, fb);
    ull r2 = add2(x2, neg2(mul2(fx2, pk2(0.693359375f, 0.693359375f))));
    r2 = add2(r2, neg2(mul2(fx2, pk2(-2.12194440e-4f, -2.12194440e-4f))));
    ull z2 = mul2(r2, r2);
    ull y2 = pk2(1.9875691500E-4f, 1.9875691500E-4f);
    y2 = fma2(y2, r2, pk2(1.3981999507E-3f, 1.3981999507E-3f));
    y2 = fma2(y2, r2, pk2(8.3334519073E-3f, 8.3334519073E-3f));
    y2 = fma2(y2, r2, pk2(4.1665795894E-2f, 4.1665795894E-2f));
    y2 = fma2(y2, r2, pk2(1.6666665459E-1f, 1.6666665459E-1f));
    y2 = fma2(y2, r2, pk2(5.0000001201E-1f, 5.0000001201E-1f));
    y2 = fma2(y2, z2, r2);
    y2 = add2(y2, pk2(1.0f, 1.0f));
    float ya, yb; up2(y2, ya, yb);
    int na = (int)fa, nb = (int)fb;
    ra = __fmul_rn(ya, __int_as_float((na + 127) << 23));
    rb = __fmul_rn(yb, __int_as_float((nb + 127) << 23));
}

__device__ __forceinline__ void xla_log2(float xa, float xb, float& ra, float& rb) {
    int ba = __float_as_int(xa), bb = __float_as_int(xb);
    float ea = (float)((ba >> 23) - 126);
    float eb = (float)((bb >> 23) - 126);
    float ma = __int_as_float((ba & 0x007fffff) | 0x3f000000);
    float mb = __int_as_float((bb & 0x007fffff) | 0x3f000000);
    if (ma < 0.707106781186547524f) {
        ea = __fsub_rn(ea, 1.0f);
        ma = __fadd_rn(__fsub_rn(ma, 1.0f), ma);
    } else {
        ma = __fsub_rn(ma, 1.0f);
    }
    if (mb < 0.707106781186547524f) {
        eb = __fsub_rn(eb, 1.0f);
        mb = __fadd_rn(__fsub_rn(mb, 1.0f), mb);
    } else {
        mb = __fsub_rn(mb, 1.0f);
    }
    ull m2 = pk2(ma, mb);
    ull z2 = mul2(m2, m2);
    ull y2 = pk2(7.0376836292E-2f, 7.0376836292E-2f);
    y2 = fma2(y2, m2, pk2(-1.1514610310E-1f, -1.1514610310E-1f));
    y2 = fma2(y2, m2, pk2(1.1676998740E-1f, 1.1676998740E-1f));
    y2 = fma2(y2, m2, pk2(-1.2420140846E-1f, -1.2420140846E-1f));
    y2 = fma2(y2, m2, pk2(1.4249322787E-1f, 1.4249322787E-1f));
    y2 = fma2(y2, m2, pk2(-1.6668057665E-1f, -1.6668057665E-1f));
    y2 = fma2(y2, m2, pk2(2.0000714765E-1f, 2.0000714765E-1f));
    y2 = fma2(y2, m2, pk2(-2.4999993993E-1f, -2.4999993993E-1f));
    y2 = fma2(y2, m2, pk2(3.3333331174E-1f, 3.3333331174E-1f));
    y2 = mul2(y2, m2);
    y2 = mul2(y2, z2);
    ull e2 = pk2(ea, eb);
    y2 = add2(y2, mul2(e2, pk2(-2.12194440e-4f, -2.12194440e-4f)));
    y2 = add2(y2, neg2(mul2(z2, pk2(0.5f, 0.5f))));
    ull res2 = add2(m2, y2);
    res2 = add2(res2, mul2(e2, pk2(0.693359375f, 0.693359375f)));
    up2(res2, ra, rb);
}

__device__ __forceinline__ float xla_log1p(float x) {
    float u = __fadd_rn(x, 1.0f);
    float w = __fmul_rn(xla_log(u), __fdiv_rn(x, __fsub_rn(u, 1.0f)));
    return (u == 1.0f) ? x : w;
}

__device__ __forceinline__ float xla_tanh(float x) {
    float xc = fminf(fmaxf(x, -7.90531110763549805f), 7.90531110763549805f);
    float x2 = __fmul_rn(xc, xc);
    float p = -2.76076847742355e-16f;
    p = __fmaf_rn(p, x2, 2.00018790482477e-13f);
    p = __fmaf_rn(p, x2, -8.60467152213735e-11f);
    p = __fmaf_rn(p, x2, 5.12229709037114e-08f);
    p = __fmaf_rn(p, x2, 1.48572235717979e-05f);
    p = __fmaf_rn(p, x2, 6.37261928875436e-04f);
    p = __fmaf_rn(p, x2, 4.89352455891786e-03f);
    float num = __fmul_rn(xc, p);
    float q = 1.19825839466702e-06f;
    q = __fmaf_rn(q, x2, 1.18534705686654e-04f);
    q = __fmaf_rn(q, x2, 2.26843463243900e-03f);
    q = __fmaf_rn(q, x2, 4.89352518554385e-03f);
    float r = __fdiv_rn(num, q);
    return (fabsf(x) < 0.0004f) ? x : r;
}

__device__ __forceinline__ float xla_sigmoid(float x) {
    return rcp_rn(__fadd_rn(1.0f, xla_exp(-x)));
}

__device__ __forceinline__ float xla_softplus(float x) {
    return __fadd_rn(fmaxf(x, 0.0f), xla_log1p(xla_exp(-fabsf(x))));
}

// packed pair softplus: per half bitwise identical to xla_softplus
__device__ __forceinline__ void xla_softplus2(float xa, float xb,
                                              float& ra, float& rb) {
    float ea, eb;
    xla_exp2(-fabsf(xa), -fabsf(xb), ea, eb);
    float ua = __fadd_rn(ea, 1.0f);
    float ub = __fadd_rn(eb, 1.0f);
    float la, lb;
    xla_log2(ua, ub, la, lb);
    float wa = __fmul_rn(la, __fdiv_rn(ea, __fsub_rn(ua, 1.0f)));
    float wb = __fmul_rn(lb, __fdiv_rn(eb, __fsub_rn(ub, 1.0f)));
    float l1a = (ua == 1.0f) ? ea : wa;
    float l1b = (ub == 1.0f) ? eb : wb;
    ra = __fadd_rn(fmaxf(xa, 0.0f), l1a);
    rb = __fadd_rn(fmaxf(xb, 0.0f), l1b);
}

// extra-bin logprob (cooperative pass): packs its two boundary sigmoids
__device__ __forceinline__ float bin_logprob_ex(int t, float m, float iv, float s) {
    if (t == 0) {
        float n0 = __fmul_rn(__fsub_rn(-0.9921875f, m), iv);
        return __fsub_rn(n0, xla_softplus(n0));
    }
    if (t == 255) {
        float n = __fmul_rn(__fsub_rn(0.9921875f, m), iv);
        return -xla_softplus(n);
    }
    float clo = __fadd_rn(__fmul_rn((float)t, 0.0078125f), -1.0f);
    float chi = __fadd_rn(__fmul_rn((float)(t + 1), 0.0078125f), -1.0f);
    float zhi = __fmul_rn(__fsub_rn(chi, m), iv);
    float zlo = __fmul_rn(__fsub_rn(clo, m), iv);
    float ehi, elo;
    xla_exp2(-zhi, -zlo, ehi, elo);
    float shi = rcp_rn(__fadd_rn(1.0f, ehi));
    float slo = rcp_rn(__fadd_rn(1.0f, elo));
    float pdf = __fsub_rn(shi, slo);
    if (pdf > 1e-5f) {
        return xla_log(fmaxf(pdf, 1e-12f));
    }
    float midc = __fadd_rn(__fmul_rn((float)(2 * t + 1), 0.00390625f), -1.0f);
    float mid = __fmul_rn(__fsub_rn(midc, m), iv);
    float mlp = __fsub_rn(__fsub_rn(mid, s), __fmul_rn(2.0f, xla_softplus(mid)));
    return __fsub_rn(mlp, LOG127_5);
}

__global__ __launch_bounds__(32 * NWARPS)
void mixlogistic_decode_kernel(const float* __restrict__ x,
                               const float* __restrict__ l,
                               const int* __restrict__ epsp,
                               float* __restrict__ out,
                               int npix)
{
    __shared__ float sLOG[NWARPS][KMIX];
    __shared__ float sLPI[NWARPS][KMIX];
    __shared__ float sM  [NWARPS][3][KMIX];
    __shared__ float sS  [NWARPS][3][KMIX];
    __shared__ float sINV[NWARPS][3][KMIX];
    __shared__ float sCF [NWARPS][3][KMIX];

    const int warp = threadIdx.x >> 5;
    const int lane = threadIdx.x & 31;
    const int P = blockIdx.x * NWARPS + warp;
    if (P >= npix) return;

    const int b  = P >> 10;
    const int hw = P & (HW - 1);

    for (int c = lane; c < 100; c += 32) {
        float v = l[(size_t)(b * 100 + c) * HW + hw];
        if (c < KMIX) {
            sLOG[warp][c] = v;
        } else {
            int cc  = (c - KMIX) / 30;
            int rem = (c - KMIX) % 30;
            int grp = rem / KMIX;
            int k   = rem % KMIX;
            if (grp == 0) {
                sM[warp][cc][k] = v;
            } else if (grp == 1) {
                float s = fmaxf(v, -7.0f);
                sS[warp][cc][k]   = s;
                sINV[warp][cc][k] = xla_exp(-s);
            } else {
                sCF[warp][cc][k] = xla_tanh(v);
            }
        }
    }
    __syncwarp();

    // cooperative log_softmax (exact fmax butterfly + parallel exp +
    // sequential ascending-k fold == XLA reduce rounding)
    {
        float lg = (lane < KMIX) ? sLOG[warp][lane] : -INFINITY;
        float mx = lg;
        #pragma unroll
        for (int off = 16; off; off >>= 1)
            mx = fmaxf(mx, __shfl_xor_sync(FULLMASK, mx, off));
        float e = xla_exp(__fsub_rn(lg, mx));
        float sum = 0.0f;
        #pragma unroll
        for (int k = 0; k < KMIX; k++)
            sum = __fadd_rn(sum, __shfl_sync(FULLMASK, e, k));
        float lsum = xla_log(sum);
        if (lane < KMIX)
            sLPI[warp][lane] = __fsub_rn(__fsub_rn(lg, mx), lsum);
    }
    __syncwarp();

    const int eps = epsp[0];
    float xr = 0.0f, xg = 0.0f;

    #pragma unroll
    for (int c = 0; c < 3; c++) {
        float xorig = x[(size_t)(b * 3 + c) * HW + hw];
        int r  = (int)(__fadd_rn(__fmul_rn(xorig, 127.5f), 127.5f));
        int lb = max(r - eps, 0);
        int ub = min(r + eps, 255);

        const int t0 = lb + lane;
        const bool v0 = (t0 <= ub);
        const float chi = __fadd_rn(__fmul_rn((float)(t0 + 1), 0.0078125f), -1.0f);

        // per-component params in lanes 0..9
        float mk = 0.0f, ivk = 0.0f, sk = 0.0f, lpik = 0.0f;
        if (lane < KMIX) {
            mk = sM[warp][c][lane];
            if (c == 1) {
                mk = __fadd_rn(mk, __fmul_rn(sCF[warp][0][lane], xr));
            } else if (c == 2) {
                mk = __fadd_rn(mk, __fmul_rn(sCF[warp][1][lane], xr));
                mk = __fadd_rn(mk, __fmul_rn(sCF[warp][2][lane], xg));
            }
            ivk  = sINV[warp][c][lane];
            sk   = sS[warp][c][lane];
            lpik = sLPI[warp][lane];
        }

        // lane-0 lower-boundary sigmoid per component (iff lb >= 1)
        float E = 0.0f;
        if (lb >= 1) {
            float cloLB = __fadd_rn(__fmul_rn((float)lb, 0.0078125f), -1.0f);
            E = xla_sigmoid(__fmul_rn(__fsub_rn(cloLB, mk), ivk));
        }

        // cooperative 33rd bin
        const int te = lb + 32;
        const bool haveExtra = (te <= ub);
        float lpe = -INFINITY;
        if (haveExtra && lane < KMIX) {
            lpe = __fadd_rn(bin_logprob_ex(te, mk, ivk, sk), lpik);
        }

        // ---- main 32 bins: components processed in packed pairs ----
        const float midc = __fadd_rn(__fmul_rn((float)(2 * t0 + 1), 0.00390625f), -1.0f);
        float lp0[KMIX];
        #pragma unroll
        for (int j = 0; j < KMIX / 2; j++) {
            const int k0 = 2 * j, k1 = 2 * j + 1;
            float m0   = __shfl_sync(FULLMASK, mk,   k0);
            float m1   = __shfl_sync(FULLMASK, mk,   k1);
            float iv0  = __shfl_sync(FULLMASK, ivk,  k0);
            float iv1  = __shfl_sync(FULLMASK, ivk,  k1);
            float s0   = __shfl_sync(FULLMASK, sk,   k0);
            float s1   = __shfl_sync(FULLMASK, sk,   k1);
            float lpi0 = __shfl_sync(FULLMASK, lpik, k0);
            float lpi1 = __shfl_sync(FULLMASK, lpik, k1);
            float E0   = __shfl_sync(FULLMASK, E,    k0);
            float E1   = __shfl_sync(FULLMASK, E,    k1);

            float zhi0 = __fmul_rn(__fsub_rn(chi, m0), iv0);
            float zhi1 = __fmul_rn(__fsub_rn(chi, m1), iv1);
            float e0, e1;
            xla_exp2(-zhi0, -zhi1, e0, e1);
            float S0 = rcp_rn(__fadd_rn(1.0f, e0));
            float S1 = rcp_rn(__fadd_rn(1.0f, e1));
            float slo0 = __shfl_up_sync(FULLMASK, S0, 1);
            float slo1 = __shfl_up_sync(FULLMASK, S1, 1);
            if (lane == 0) { slo0 = E0; slo1 = E1; }

            float pdf0 = __fsub_rn(S0, slo0);
            float pdf1 = __fsub_rn(S1, slo1);
            float lg0, lg1;
            xla_log2(fmaxf(pdf0, 1e-12f), fmaxf(pdf1, 1e-12f), lg0, lg1);

            float lpA, lpB;
            if (t0 == 0) {
                float spA, spB;
                xla_softplus2(zhi0, zhi1, spA, spB);
                lpA = __fsub_rn(zhi0, spA);
                lpB = __fsub_rn(zhi1, spB);
            } else if (t0 == 255) {
                float zloA = __fmul_rn(__fsub_rn(0.9921875f, m0), iv0);
                float zloB = __fmul_rn(__fsub_rn(0.9921875f, m1), iv1);
                float spA, spB;
                xla_softplus2(zloA, zloB, spA, spB);
                lpA = -spA;
                lpB = -spB;
            } else {
                lpA = lg0;
                lpB = lg1;
                bool f0 = !(pdf0 > 1e-5f);
                bool f1 = !(pdf1 > 1e-5f);
                if (f0 || f1) {   // packed fallback: both halves computed
                    float mid0 = __fmul_rn(__fsub_rn(midc, m0), iv0);
                    float mid1 = __fmul_rn(__fsub_rn(midc, m1), iv1);
                    float sp0, sp1;
                    xla_softplus2(mid0, mid1, sp0, sp1);
                    float a0 = __fsub_rn(__fsub_rn(__fsub_rn(mid0, s0),
                                                   __fmul_rn(2.0f, sp0)), LOG127_5);
                    float a1 = __fsub_rn(__fsub_rn(__fsub_rn(mid1, s1),
                                                   __fmul_rn(2.0f, sp1)), LOG127_5);
                    if (f0) lpA = a0;
                    if (f1) lpB = a1;
                }
            }
            lp0[k0] = __fadd_rn(lpA, lpi0);
            lp0[k1] = __fadd_rn(lpB, lpi1);
        }

        // per-bin logsumexp over k (sequential ascending k; packed sub + exps)
        float bv = -INFINITY;
        int   bt = 0x7FFFFFFF;
        if (v0) {
            float amax = lp0[0];
            #pragma unroll
            for (int k = 1; k < KMIX; k++) amax = fmaxf(amax, lp0[k]);
            ull am2 = pk2(amax, amax);
            float ex[KMIX];
            #pragma unroll
            for (int j = 0; j < KMIX / 2; j++) {
                float da, db;
                up2(add2(pk2(lp0[2 * j], lp0[2 * j + 1]), neg2(am2)), da, db);
                xla_exp2(da, db, ex[2 * j], ex[2 * j + 1]);
            }
            float sum = 0.0f;
            #pragma unroll
            for (int k = 0; k < KMIX; k++) sum = __fadd_rn(sum, ex[k]);
            bv = __fadd_rn(xla_log(sum), amax);
            bt = t0;
        }

        // warp argmax (first-index tie semantics)
        #pragma unroll
        for (int off = 16; off; off >>= 1) {
            float ov = __shfl_down_sync(FULLMASK, bv, off);
            int   ot = __shfl_down_sync(FULLMASK, bt, off);
            if (ov > bv || (ov == bv && ot < bt)) { bv = ov; bt = ot; }
        }

        // extra-bin logsumexp (uniform result; final compare on lane 0)
        if (haveExtra) {
            float amax = lpe;
            #pragma unroll
            for (int off = 16; off; off >>= 1)
                amax = fmaxf(amax, __shfl_xor_sync(FULLMASK, amax, off));
            float e = xla_exp(__fsub_rn(lpe, amax));
            float sum = 0.0f;
            #pragma unroll
            for (int k = 0; k < KMIX; k++)
                sum = __fadd_rn(sum, __shfl_sync(FULLMASK, e, k));
            float val = __fadd_rn(xla_log(sum), amax);
            if (lane == 0 && val > bv) { bv = val; bt = te; }
        }

        bt = __shfl_sync(FULLMASK, bt, 0);

        float outv = __fdiv_rn(__fsub_rn((float)bt, 127.5f), 127.5f);
        if (c == 0) xr = outv;
        else if (c == 1) xg = outv;

        if (lane == 0) {
            out[(size_t)(b * 3 + c) * HW + hw] = outv;
        }
    }
}

extern "C" void kernel_launch(void* const* d_in, const int* in_sizes, int n_in,
                              void* d_out, int out_size)
{
    const float* x   = (const float*)d_in[0];
    const float* l   = (const float*)d_in[1];
    const int*   eps = (const int*)d_in[2];
    float* out = (float*)d_out;

    int npix = in_sizes[0] / 3;
    int blocks = (npix + NWARPS - 1) / NWARPS;
    mixlogistic_decode_kernel<<<blocks, 32 * NWARPS>>>(x, l, eps, out, npix);
}

// round 13
// speedup vs baseline: 1.1319x; 1.0135x over previous
#include <cuda_runtime.h>

// Math replicates XLA:CPU cephes/Eigen lowering bit-for-bit (validated R5-R12).
// f32x2 packed ops do two independent IEEE-rn f32 ops -> bitwise identical per
// half. rcp.rn(x) == div.rn(1,x) bitwise (validated R10+).
// Params via shuffle-broadcast (smem float4 path regressed, R10).
// NWARPS=4: 128-thread blocks quantize occupancy at 11 blocks x 4 = 44 warps/SM
// (vs 40 with 256-thread blocks) at the same 46 regs.

#define FULLMASK 0xFFFFFFFFu
#define NWARPS 4
#define KMIX 10
#define HW 1024
#define LOG127_5 4.8481163645984802f

typedef unsigned long long ull;

__device__ __forceinline__ ull pk2(float a, float b) {
    ull r; asm("mov.b64 %0,{%1,%2};" : "=l"(r) : "f"(a), "f"(b)); return r;
}
__device__ __forceinline__ void up2(ull p, float& a, float& b) {
    asm("mov.b64 {%0,%1},%2;" : "=f"(a), "=f"(b) : "l"(p));
}
__device__ __forceinline__ ull mul2(ull a, ull b) {
    ull r; asm("mul.rn.f32x2 %0,%1,%2;" : "=l"(r) : "l"(a), "l"(b)); return r;
}
__device__ __forceinline__ ull add2(ull a, ull b) {
    ull r; asm("add.rn.f32x2 %0,%1,%2;" : "=l"(r) : "l"(a), "l"(b)); return r;
}
__device__ __forceinline__ ull fma2(ull a, ull b, ull c) {
    ull r; asm("fma.rn.f32x2 %0,%1,%2,%3;" : "=l"(r) : "l"(a), "l"(b), "l"(c)); return r;
}
__device__ __forceinline__ ull neg2(ull a) { return a ^ 0x8000000080000000ull; }
__device__ __forceinline__ float rcp_rn(float x) {
    float r; asm("rcp.rn.f32 %0,%1;" : "=f"(r) : "f"(x)); return r;
}

// ---- scalar cephes exp/log (reference-bit-exact) ----
__device__ __forceinline__ float xla_exp(float x) {
    x = fminf(fmaxf(x, -88.3762626647949f), 88.3762626647950f);
    float fx = floorf(__fmaf_rn(x, 1.44269504088896341f, 0.5f));
    float r = __fsub_rn(x, __fmul_rn(fx, 0.693359375f));
    r = __fsub_rn(r, __fmul_rn(fx, -2.12194440e-4f));
    float z = __fmul_rn(r, r);
    float y = 1.9875691500E-4f;
    y = __fmaf_rn(y, r, 1.3981999507E-3f);
    y = __fmaf_rn(y, r, 8.3334519073E-3f);
    y = __fmaf_rn(y, r, 4.1665795894E-2f);
    y = __fmaf_rn(y, r, 1.6666665459E-1f);
    y = __fmaf_rn(y, r, 5.0000001201E-1f);
    y = __fmaf_rn(y, z, r);
    y = __fadd_rn(y, 1.0f);
    int n = (int)fx;
    return __fmul_rn(y, __int_as_float((n + 127) << 23));
}

__device__ __forceinline__ float xla_log(float x) {
    int bits = __float_as_int(x);
    float e = (float)((bits >> 23) - 126);
    float m = __int_as_float((bits & 0x007fffff) | 0x3f000000);
    if (m < 0.707106781186547524f) {
        e = __fsub_rn(e, 1.0f);
        m = __fadd_rn(__fsub_rn(m, 1.0f), m);
    } else {
        m = __fsub_rn(m, 1.0f);
    }
    float z = __fmul_rn(m, m);
    float y = 7.0376836292E-2f;
    y = __fmaf_rn(y, m, -1.1514610310E-1f);
    y = __fmaf_rn(y, m, 1.1676998740E-1f);
    y = __fmaf_rn(y, m, -1.2420140846E-1f);
    y = __fmaf_rn(y, m, 1.4249322787E-1f);
    y = __fmaf_rn(y, m, -1.6668057665E-1f);
    y = __fmaf_rn(y, m, 2.0000714765E-1f);
    y = __fmaf_rn(y, m, -2.4999993993E-1f);
    y = __fmaf_rn(y, m, 3.3333331174E-1f);
    y = __fmul_rn(y, m);
    y = __fmul_rn(y, z);
    y = __fadd_rn(y, __fmul_rn(e, -2.12194440e-4f));
    y = __fsub_rn(y, __fmul_rn(z, 0.5f));
    float res = __fadd_rn(m, y);
    res = __fadd_rn(res, __fmul_rn(e, 0.693359375f));
    return res;
}

// ---- packed-pair exp/log: bitwise identical per half to scalar versions ----
__device__ __forceinline__ void xla_exp2(float xa, float xb, float& ra, float& rb) {
    xa = fminf(fmaxf(xa, -88.3762626647949f), 88.3762626647950f);
    xb = fminf(fmaxf(xb, -88.3762626647949f), 88.3762626647950f);
    ull x2 = pk2(xa, xb);
    ull fx2 = fma2(x2, pk2(1.44269504088896341f, 1.44269504088896341f),
                   pk2(0.5f, 0.5f));
    float fa, fb; up2(fx2, fa, fb);
    fa = floorf(fa); fb = floorf(fb);
    fx2 = pk2(fa, fb);
    ull r2 = add2(x2, neg2(mul2(fx2, pk2(0.693359375f, 0.693359375f))));
    r2 = add2(r2, neg2(mul2(fx2, pk2(-2.12194440e-4f, -2.12194440e-4f))));
    ull z2 = mul2(r2, r2);
    ull y2 = pk2(1.9875691500E-4f, 1.9875691500E-4f);
    y2 = fma2(y2, r2, pk2(1.3981999507E-3f, 1.3981999507E-3f));
    y2 = fma2(y2, r2, pk2(8.3334519073E-3f, 8.3334519073E-3f));
    y2 = fma2(y2, r2, pk2(4.1665795894E-2f, 4.1665795894E-2f));
    y2 = fma2(y2, r2, pk2(1.6666665459E-1f, 1.6666665459E-1f));
    y2 = fma2(y2, r2, pk2(5.0000001201E-1f, 5.0000001201E-1f));
    y2 = fma2(y2, z2, r2);
    y2 = add2(y2, pk2(1.0f, 1.0f));
    float ya, yb; up2(y2, ya, yb);
    int na = (int)fa, nb = (int)fb;
    ra = __fmul_rn(ya, __int_as_float((na + 127) << 23));
    rb = __fmul_rn(yb, __int_as_float((nb + 127) << 23));
}

__device__ __forceinline__ void xla_log2(float xa, float xb, float& ra, float& rb) {
    int ba = __float_as_int(xa), bb = __float_as_int(xb);
    float ea = (float)((ba >> 23) - 126);
    float eb = (float)((bb >> 23) - 126);
    float ma = __int_as_float((ba & 0x007fffff) | 0x3f000000);
    float mb = __int_as_float((bb & 0x007fffff) | 0x3f000000);
    if (ma < 0.707106781186547524f) {
        ea = __fsub_rn(ea, 1.0f);
        ma = __fadd_rn(__fsub_rn(ma, 1.0f), ma);
    } else {
        ma = __fsub_rn(ma, 1.0f);
    }
    if (mb < 0.707106781186547524f) {
        eb = __fsub_rn(eb, 1.0f);
        mb = __fadd_rn(__fsub_rn(mb, 1.0f), mb);
    } else {
        mb = __fsub_rn(mb, 1.0f);
    }
    ull m2 = pk2(ma, mb);
    ull z2 = mul2(m2, m2);
    ull y2 = pk2(7.0376836292E-2f, 7.0376836292E-2f);
    y2 = fma2(y2, m2, pk2(-1.1514610310E-1f, -1.1514610310E-1f));
    y2 = fma2(y2, m2, pk2(1.1676998740E-1f, 1.1676998740E-1f));
    y2 = fma2(y2, m2, pk2(-1.2420140846E-1f, -1.2420140846E-1f));
    y2 = fma2(y2, m2, pk2(1.4249322787E-1f, 1.4249322787E-1f));
    y2 = fma2(y2, m2, pk2(-1.6668057665E-1f, -1.6668057665E-1f));
    y2 = fma2(y2, m2, pk2(2.0000714765E-1f, 2.0000714765E-1f));
    y2 = fma2(y2, m2, pk2(-2.4999993993E-1f, -2.4999993993E-1f));
    y2 = fma2(y2, m2, pk2(3.3333331174E-1f, 3.3333331174E-1f));
    y2 = mul2(y2, m2);
    y2 = mul2(y2, z2);
    ull e2 = pk2(ea, eb);
    y2 = add2(y2, mul2(e2, pk2(-2.12194440e-4f, -2.12194440e-4f)));
    y2 = add2(y2, neg2(mul2(z2, pk2(0.5f, 0.5f))));
    ull res2 = add2(m2, y2);
    res2 = add2(res2, mul2(e2, pk2(0.693359375f, 0.693359375f)));
    up2(res2, ra, rb);
}

__device__ __forceinline__ float xla_log1p(float x) {
    float u = __fadd_rn(x, 1.0f);
    float w = __fmul_rn(xla_log(u), __fdiv_rn(x, __fsub_rn(u, 1.0f)));
    return (u == 1.0f) ? x : w;
}

__device__ __forceinline__ float xla_tanh(float x) {
    float xc = fminf(fmaxf(x, -7.90531110763549805f), 7.90531110763549805f);
    float x2 = __fmul_rn(xc, xc);
    float p = -2.76076847742355e-16f;
    p = __fmaf_rn(p, x2, 2.00018790482477e-13f);
    p = __fmaf_rn(p, x2, -8.60467152213735e-11f);
    p = __fmaf_rn(p, x2, 5.12229709037114e-08f);
    p = __fmaf_rn(p, x2, 1.48572235717979e-05f);
    p = __fmaf_rn(p, x2, 6.37261928875436e-04f);
    p = __fmaf_rn(p, x2, 4.89352455891786e-03f);
    float num = __fmul_rn(xc, p);
    float q = 1.19825839466702e-06f;
    q = __fmaf_rn(q, x2, 1.18534705686654e-04f);
    q = __fmaf_rn(q, x2, 2.26843463243900e-03f);
    q = __fmaf_rn(q, x2, 4.89352518554385e-03f);
    float r = __fdiv_rn(num, q);
    return (fabsf(x) < 0.0004f) ? x : r;
}

__device__ __forceinline__ float xla_sigmoid(float x) {
    return rcp_rn(__fadd_rn(1.0f, xla_exp(-x)));
}

__device__ __forceinline__ float xla_softplus(float x) {
    return __fadd_rn(fmaxf(x, 0.0f), xla_log1p(xla_exp(-fabsf(x))));
}

// packed pair softplus: per half bitwise identical to xla_softplus
__device__ __forceinline__ void xla_softplus2(float xa, float xb,
                                              float& ra, float& rb) {
    float ea, eb;
    xla_exp2(-fabsf(xa), -fabsf(xb), ea, eb);
    float ua = __fadd_rn(ea, 1.0f);
    float ub = __fadd_rn(eb, 1.0f);
    float la, lb;
    xla_log2(ua, ub, la, lb);
    float wa = __fmul_rn(la, __fdiv_rn(ea, __fsub_rn(ua, 1.0f)));
    float wb = __fmul_rn(lb, __fdiv_rn(eb, __fsub_rn(ub, 1.0f)));
    float l1a = (ua == 1.0f) ? ea : wa;
    float l1b = (ub == 1.0f) ? eb : wb;
    ra = __fadd_rn(fmaxf(xa, 0.0f), l1a);
    rb = __fadd_rn(fmaxf(xb, 0.0f), l1b);
}

// extra-bin logprob (cooperative pass): packs its two boundary sigmoids
__device__ __forceinline__ float bin_logprob_ex(int t, float m, float iv, float s) {
    if (t == 0) {
        float n0 = __fmul_rn(__fsub_rn(-0.9921875f, m), iv);
        return __fsub_rn(n0, xla_softplus(n0));
    }
    if (t == 255) {
        float n = __fmul_rn(__fsub_rn(0.9921875f, m), iv);
        return -xla_softplus(n);
    }
    float clo = __fadd_rn(__fmul_rn((float)t, 0.0078125f), -1.0f);
    float chi = __fadd_rn(__fmul_rn((float)(t + 1), 0.0078125f), -1.0f);
    float zhi = __fmul_rn(__fsub_rn(chi, m), iv);
    float zlo = __fmul_rn(__fsub_rn(clo, m), iv);
    float ehi, elo;
    xla_exp2(-zhi, -zlo, ehi, elo);
    float shi = rcp_rn(__fadd_rn(1.0f, ehi));
    float slo = rcp_rn(__fadd_rn(1.0f, elo));
    float pdf = __fsub_rn(shi, slo);
    if (pdf > 1e-5f) {
        return xla_log(fmaxf(pdf, 1e-12f));
    }
    float midc = __fadd_rn(__fmul_rn((float)(2 * t + 1), 0.00390625f), -1.0f);
    float mid = __fmul_rn(__fsub_rn(midc, m), iv);
    float mlp = __fsub_rn(__fsub_rn(mid, s), __fmul_rn(2.0f, xla_softplus(mid)));
    return __fsub_rn(mlp, LOG127_5);
}

__global__ __launch_bounds__(32 * NWARPS)
void mixlogistic_decode_kernel(const float* __restrict__ x,
                               const float* __restrict__ l,
                               const int* __restrict__ epsp,
                               float* __restrict__ out,
                               int npix)
{
    __shared__ float sLOG[NWARPS][KMIX];
    __shared__ float sLPI[NWARPS][KMIX];
    __shared__ float sM  [NWARPS][3][KMIX];
    __shared__ float sS  [NWARPS][3][KMIX];
    __shared__ float sINV[NWARPS][3][KMIX];
    __shared__ float sCF [NWARPS][3][KMIX];

    const int warp = threadIdx.x >> 5;
    const int lane = threadIdx.x & 31;
    const int P = blockIdx.x * NWARPS + warp;
    if (P >= npix) return;

    const int b  = P >> 10;
    const int hw = P & (HW - 1);

    // preload the 3 warp-uniform x values (overlaps with preamble math)
    const float x0 = x[(size_t)(b * 3 + 0) * HW + hw];
    const float x1 = x[(size_t)(b * 3 + 1) * HW + hw];
    const float x2v = x[(size_t)(b * 3 + 2) * HW + hw];

    for (int c = lane; c < 100; c += 32) {
        float v = l[(size_t)(b * 100 + c) * HW + hw];
        if (c < KMIX) {
            sLOG[warp][c] = v;
        } else {
            int cc  = (c - KMIX) / 30;
            int rem = (c - KMIX) % 30;
            int grp = rem / KMIX;
            int k   = rem % KMIX;
            if (grp == 0) {
                sM[warp][cc][k] = v;
            } else if (grp == 1) {
                float s = fmaxf(v, -7.0f);
                sS[warp][cc][k]   = s;
                sINV[warp][cc][k] = xla_exp(-s);
            } else {
                sCF[warp][cc][k] = xla_tanh(v);
            }
        }
    }
    __syncwarp();

    // cooperative log_softmax (exact fmax butterfly + parallel exp +
    // sequential ascending-k fold == XLA reduce rounding)
    {
        float lg = (lane < KMIX) ? sLOG[warp][lane] : -INFINITY;
        float mx = lg;
        #pragma unroll
        for (int off = 16; off; off >>= 1)
            mx = fmaxf(mx, __shfl_xor_sync(FULLMASK, mx, off));
        float e = xla_exp(__fsub_rn(lg, mx));
        float sum = 0.0f;
        #pragma unroll
        for (int k = 0; k < KMIX; k++)
            sum = __fadd_rn(sum, __shfl_sync(FULLMASK, e, k));
        float lsum = xla_log(sum);
        if (lane < KMIX)
            sLPI[warp][lane] = __fsub_rn(__fsub_rn(lg, mx), lsum);
    }
    __syncwarp();

    const int eps = epsp[0];
    float xr = 0.0f, xg = 0.0f;

    #pragma unroll
    for (int c = 0; c < 3; c++) {
        float xorig = (c == 0) ? x0 : (c == 1) ? x1 : x2v;
        int r  = (int)(__fadd_rn(__fmul_rn(xorig, 127.5f), 127.5f));
        int lb = max(r - eps, 0);
        int ub = min(r + eps, 255);

        const int t0 = lb + lane;
        const bool v0 = (t0 <= ub);
        const float chi = __fadd_rn(__fmul_rn((float)(t0 + 1), 0.0078125f), -1.0f);

        // per-component params in lanes 0..9
        float mk = 0.0f, ivk = 0.0f, sk = 0.0f, lpik = 0.0f;
        if (lane < KMIX) {
            mk = sM[warp][c][lane];
            if (c == 1) {
                mk = __fadd_rn(mk, __fmul_rn(sCF[warp][0][lane], xr));
            } else if (c == 2) {
                mk = __fadd_rn(mk, __fmul_rn(sCF[warp][1][lane], xr));
                mk = __fadd_rn(mk, __fmul_rn(sCF[warp][2][lane], xg));
            }
            ivk  = sINV[warp][c][lane];
            sk   = sS[warp][c][lane];
            lpik = sLPI[warp][lane];
        }

        // lane-0 lower-boundary sigmoid per component (iff lb >= 1)
        float E = 0.0f;
        if (lb >= 1) {
            float cloLB = __fadd_rn(__fmul_rn((float)lb, 0.0078125f), -1.0f);
            E = xla_sigmoid(__fmul_rn(__fsub_rn(cloLB, mk), ivk));
        }

        // cooperative 33rd bin
        const int te = lb + 32;
        const bool haveExtra = (te <= ub);
        float lpe = -INFINITY;
        if (haveExtra && lane < KMIX) {
            lpe = __fadd_rn(bin_logprob_ex(te, mk, ivk, sk), lpik);
        }

        // ---- main 32 bins: components processed in packed pairs ----
        const float midc = __fadd_rn(__fmul_rn((float)(2 * t0 + 1), 0.00390625f), -1.0f);
        float lp0[KMIX];
        #pragma unroll
        for (int j = 0; j < KMIX / 2; j++) {
            const int k0 = 2 * j, k1 = 2 * j + 1;
            float m0   = __shfl_sync(FULLMASK, mk,   k0);
            float m1   = __shfl_sync(FULLMASK, mk,   k1);
            float iv0  = __shfl_sync(FULLMASK, ivk,  k0);
            float iv1  = __shfl_sync(FULLMASK, ivk,  k1);
            float s0   = __shfl_sync(FULLMASK, sk,   k0);
            float s1   = __shfl_sync(FULLMASK, sk,   k1);
            float lpi0 = __shfl_sync(FULLMASK, lpik, k0);
            float lpi1 = __shfl_sync(FULLMASK, lpik, k1);
            float E0   = __shfl_sync(FULLMASK, E,    k0);
            float E1   = __shfl_sync(FULLMASK, E,    k1);

            float zhi0 = __fmul_rn(__fsub_rn(chi, m0), iv0);
            float zhi1 = __fmul_rn(__fsub_rn(chi, m1), iv1);
            float e0, e1;
            xla_exp2(-zhi0, -zhi1, e0, e1);
            float S0 = rcp_rn(__fadd_rn(1.0f, e0));
            float S1 = rcp_rn(__fadd_rn(1.0f, e1));
            float slo0 = __shfl_up_sync(FULLMASK, S0, 1);
            float slo1 = __shfl_up_sync(FULLMASK, S1, 1);
            if (lane == 0) { slo0 = E0; slo1 = E1; }

            float pdf0 = __fsub_rn(S0, slo0);
            float pdf1 = __fsub_rn(S1, slo1);
            float lg0, lg1;
            xla_log2(fmaxf(pdf0, 1e-12f), fmaxf(pdf1, 1e-12f), lg0, lg1);

            float lpA, lpB;
            if (t0 == 0) {
                float spA, spB;
                xla_softplus2(zhi0, zhi1, spA, spB);
                lpA = __fsub_rn(zhi0, spA);
                lpB = __fsub_rn(zhi1, spB);
            } else if (t0 == 255) {
                float zloA = __fmul_rn(__fsub_rn(0.9921875f, m0), iv0);
                float zloB = __fmul_rn(__fsub_rn(0.9921875f, m1), iv1);
                float spA, spB;
                xla_softplus2(zloA, zloB, spA, spB);
                lpA = -spA;
                lpB = -spB;
            } else {
                lpA = lg0;
                lpB = lg1;
                bool f0 = !(pdf0 > 1e-5f);
                bool f1 = !(pdf1 > 1e-5f);
                if (f0 || f1) {   // packed fallback: both halves computed
                    float mid0 = __fmul_rn(__fsub_rn(midc, m0), iv0);
                    float mid1 = __fmul_rn(__fsub_rn(midc, m1), iv1);
                    float sp0, sp1;
                    xla_softplus2(mid0, mid1, sp0, sp1);
                    float a0 = __fsub_rn(__fsub_rn(__fsub_rn(mid0, s0),
                                                   __fmul_rn(2.0f, sp0)), LOG127_5);
                    float a1 = __fsub_rn(__fsub_rn(__fsub_rn(mid1, s1),
                                                   __fmul_rn(2.0f, sp1)), LOG127_5);
                    if (f0) lpA = a0;
                    if (f1) lpB = a1;
                }
            }
            lp0[k0] = __fadd_rn(lpA, lpi0);
            lp0[k1] = __fadd_rn(lpB, lpi1);
        }

        // per-bin logsumexp over k (sequential ascending k; packed sub + exps)
        float bv = -INFINITY;
        int   bt = 0x7FFFFFFF;
        if (v0) {
            float amax = lp0[0];
            #pragma unroll
            for (int k = 1; k < KMIX; k++) amax = fmaxf(amax, lp0[k]);
            ull am2 = pk2(amax, amax);
            float ex[KMIX];
            #pragma unroll
            for (int j = 0; j < KMIX / 2; j++) {
                float da, db;
                up2(add2(pk2(lp0[2 * j], lp0[2 * j + 1]), neg2(am2)), da, db);
                xla_exp2(da, db, ex[2 * j], ex[2 * j + 1]);
            }
            float sum = 0.0f;
            #pragma unroll
            for (int k = 0; k < KMIX; k++) sum = __fadd_rn(sum, ex[k]);
            bv = __fadd_rn(xla_log(sum), amax);
            bt = t0;
        }

        // warp argmax (first-index tie semantics)
        #pragma unroll
        for (int off = 16; off; off >>= 1) {
            float ov = __shfl_down_sync(FULLMASK, bv, off);
            int   ot = __shfl_down_sync(FULLMASK, bt, off);
            if (ov > bv || (ov == bv && ot < bt)) { bv = ov; bt = ot; }
        }

        // extra-bin logsumexp (uniform result; final compare on lane 0)
        if (haveExtra) {
            float amax = lpe;
            #pragma unroll
            for (int off = 16; off; off >>= 1)
                amax = fmaxf(amax, __shfl_xor_sync(FULLMASK, amax, off));
            float e = xla_exp(__fsub_rn(lpe, amax));
            float sum = 0.0f;
            #pragma unroll
            for (int k = 0; k < KMIX; k++)
                sum = __fadd_rn(sum, __shfl_sync(FULLMASK, e, k));
            float val = __fadd_rn(xla_log(sum), amax);
            if (lane == 0 && val > bv) { bv = val; bt = te; }
        }

        bt = __shfl_sync(FULLMASK, bt, 0);

        float outv = __fdiv_rn(__fsub_rn((float)bt, 127.5f), 127.5f);
        if (c == 0) xr = outv;
        else if (c == 1) xg = outv;

        if (lane == 0) {
            out[(size_t)(b * 3 + c) * HW + hw] = outv;
        }
    }
}

extern "C" void kernel_launch(void* const* d_in, const int* in_sizes, int n_in,
                              void* d_out, int out_size)
{
    const float* x   = (const float*)d_in[0];
    const float* l   = (const float*)d_in[1];
    const int*   eps = (const int*)d_in[2];
    float* out = (float*)d_out;

    int npix = in_sizes[0] / 3;
    int blocks = (npix + NWARPS - 1) / NWARPS;   // 4096 blocks of 128 threads
    mixlogistic_decode_kernel<<<blocks, 32 * NWARPS>>>(x, l, eps, out, npix);
}

// round 14
// speedup vs baseline: 1.4470x; 1.2784x over previous
#include <cuda_runtime.h>

// Math replicates XLA:CPU cephes/Eigen lowering bit-for-bit (validated R5-R13).
// f32x2 packed ops do two independent IEEE-rn f32 ops -> bitwise identical per
// half. rcp.rn(x) == div.rn(1,x) bitwise (validated R10+).
// Params via shuffle-broadcast (smem float4 path regressed, R10).
// NWARPS=8 (R13's 4-warp blocks regressed). Boundary bins (t=0/255) handled by
// post-loop warp-uniform fixups instead of divergent in-loop branches.

#define FULLMASK 0xFFFFFFFFu
#define NWARPS 8
#define KMIX 10
#define HW 1024
#define LOG127_5 4.8481163645984802f

typedef unsigned long long ull;

__device__ __forceinline__ ull pk2(float a, float b) {
    ull r; asm("mov.b64 %0,{%1,%2};" : "=l"(r) : "f"(a), "f"(b)); return r;
}
__device__ __forceinline__ void up2(ull p, float& a, float& b) {
    asm("mov.b64 {%0,%1},%2;" : "=f"(a), "=f"(b) : "l"(p));
}
__device__ __forceinline__ ull mul2(ull a, ull b) {
    ull r; asm("mul.rn.f32x2 %0,%1,%2;" : "=l"(r) : "l"(a), "l"(b)); return r;
}
__device__ __forceinline__ ull add2(ull a, ull b) {
    ull r; asm("add.rn.f32x2 %0,%1,%2;" : "=l"(r) : "l"(a), "l"(b)); return r;
}
__device__ __forceinline__ ull fma2(ull a, ull b, ull c) {
    ull r; asm("fma.rn.f32x2 %0,%1,%2,%3;" : "=l"(r) : "l"(a), "l"(b), "l"(c)); return r;
}
__device__ __forceinline__ ull neg2(ull a) { return a ^ 0x8000000080000000ull; }
__device__ __forceinline__ float rcp_rn(float x) {
    float r; asm("rcp.rn.f32 %0,%1;" : "=f"(r) : "f"(x)); return r;
}

// ---- scalar cephes exp/log (reference-bit-exact) ----
__device__ __forceinline__ float xla_exp(float x) {
    x = fminf(fmaxf(x, -88.3762626647949f), 88.3762626647950f);
    float fx = floorf(__fmaf_rn(x, 1.44269504088896341f, 0.5f));
    float r = __fsub_rn(x, __fmul_rn(fx, 0.693359375f));
    r = __fsub_rn(r, __fmul_rn(fx, -2.12194440e-4f));
    float z = __fmul_rn(r, r);
    float y = 1.9875691500E-4f;
    y = __fmaf_rn(y, r, 1.3981999507E-3f);
    y = __fmaf_rn(y, r, 8.3334519073E-3f);
    y = __fmaf_rn(y, r, 4.1665795894E-2f);
    y = __fmaf_rn(y, r, 1.6666665459E-1f);
    y = __fmaf_rn(y, r, 5.0000001201E-1f);
    y = __fmaf_rn(y, z, r);
    y = __fadd_rn(y, 1.0f);
    int n = (int)fx;
    return __fmul_rn(y, __int_as_float((n + 127) << 23));
}

__device__ __forceinline__ float xla_log(float x) {
    int bits = __float_as_int(x);
    float e = (float)((bits >> 23) - 126);
    float m = __int_as_float((bits & 0x007fffff) | 0x3f000000);
    if (m < 0.707106781186547524f) {
        e = __fsub_rn(e, 1.0f);
        m = __fadd_rn(__fsub_rn(m, 1.0f), m);
    } else {
        m = __fsub_rn(m, 1.0f);
    }
    float z = __fmul_rn(m, m);
    float y = 7.0376836292E-2f;
    y = __fmaf_rn(y, m, -1.1514610310E-1f);
    y = __fmaf_rn(y, m, 1.1676998740E-1f);
    y = __fmaf_rn(y, m, -1.2420140846E-1f);
    y = __fmaf_rn(y, m, 1.4249322787E-1f);
    y = __fmaf_rn(y, m, -1.6668057665E-1f);
    y = __fmaf_rn(y, m, 2.0000714765E-1f);
    y = __fmaf_rn(y, m, -2.4999993993E-1f);
    y = __fmaf_rn(y, m, 3.3333331174E-1f);
    y = __fmul_rn(y, m);
    y = __fmul_rn(y, z);
    y = __fadd_rn(y, __fmul_rn(e, -2.12194440e-4f));
    y = __fsub_rn(y, __fmul_rn(z, 0.5f));
    float res = __fadd_rn(m, y);
    res = __fadd_rn(res, __fmul_rn(e, 0.693359375f));
    return res;
}

// ---- packed-pair exp/log: bitwise identical per half to scalar versions ----
__device__ __forceinline__ void xla_exp2(float xa, float xb, float& ra, float& rb) {
    xa = fminf(fmaxf(xa, -88.3762626647949f), 88.3762626647950f);
    xb = fminf(fmaxf(xb, -88.3762626647949f), 88.3762626647950f);
    ull x2 = pk2(xa, xb);
    ull fx2 = fma2(x2, pk2(1.44269504088896341f, 1.44269504088896341f),
                   pk2(0.5f, 0.5f));
    float fa, fb; up2(fx2, fa, fb);
    fa = floorf(fa); fb = floorf(fb);
    fx2 = pk2(fa, fb);
    ull r2 = add2(x2, neg2(mul2(fx2, pk2(0.693359375f, 0.693359375f))));
    r2 = add2(r2, neg2(mul2(fx2, pk2(-2.12194440e-4f, -2.12194440e-4f))));
    ull z2 = mul2(r2, r2);
    ull y2 = pk2(1.9875691500E-4f, 1.9875691500E-4f);
    y2 = fma2(y2, r2, pk2(1.3981999507E-3f, 1.3981999507E-3f));
    y2 = fma2(y2, r2, pk2(8.3334519073E-3f, 8.3334519073E-3f));
    y2 = fma2(y2, r2, pk2(4.1665795894E-2f, 4.1665795894E-2f));
    y2 = fma2(y2, r2, pk2(1.6666665459E-1f, 1.6666665459E-1f));
    y2 = fma2(y2, r2, pk2(5.0000001201E-1f, 5.0000001201E-1f));
    y2 = fma2(y2, z2, r2);
    y2 = add2(y2, pk2(1.0f, 1.0f));
    float ya, yb; up2(y2, ya, yb);
    int na = (int)fa, nb = (int)fb;
    ra = __fmul_rn(ya, __int_as_float((na + 127) << 23));
    rb = __fmul_rn(yb, __int_as_float((nb + 127) << 23));
}

__device__ __forceinline__ void xla_log2(float xa, float xb, float& ra, float& rb) {
    int ba = __float_as_int(xa), bb = __float_as_int(xb);
    float ea = (float)((ba >> 23) - 126);
    float eb = (float)((bb >> 23) - 126);
    float ma = __int_as_float((ba & 0x007fffff) | 0x3f000000);
    float mb = __int_as_float((bb & 0x007fffff) | 0x3f000000);
    if (ma < 0.707106781186547524f) {
        ea = __fsub_rn(ea, 1.0f);
        ma = __fadd_rn(__fsub_rn(ma, 1.0f), ma);
    } else {
        ma = __fsub_rn(ma, 1.0f);
    }
    if (mb < 0.707106781186547524f) {
        eb = __fsub_rn(eb, 1.0f);
        mb = __fadd_rn(__fsub_rn(mb, 1.0f), mb);
    } else {
        mb = __fsub_rn(mb, 1.0f);
    }
    ull m2 = pk2(ma, mb);
    ull z2 = mul2(m2, m2);
    ull y2 = pk2(7.0376836292E-2f, 7.0376836292E-2f);
    y2 = fma2(y2, m2, pk2(-1.1514610310E-1f, -1.1514610310E-1f));
    y2 = fma2(y2, m2, pk2(1.1676998740E-1f, 1.1676998740E-1f));
    y2 = fma2(y2, m2, pk2(-1.2420140846E-1f, -1.2420140846E-1f));
    y2 = fma2(y2, m2, pk2(1.4249322787E-1f, 1.4249322787E-1f));
    y2 = fma2(y2, m2, pk2(-1.6668057665E-1f, -1.6668057665E-1f));
    y2 = fma2(y2, m2, pk2(2.0000714765E-1f, 2.0000714765E-1f));
    y2 = fma2(y2, m2, pk2(-2.4999993993E-1f, -2.4999993993E-1f));
    y2 = fma2(y2, m2, pk2(3.3333331174E-1f, 3.3333331174E-1f));
    y2 = mul2(y2, m2);
    y2 = mul2(y2, z2);
    ull e2 = pk2(ea, eb);
    y2 = add2(y2, mul2(e2, pk2(-2.12194440e-4f, -2.12194440e-4f)));
    y2 = add2(y2, neg2(mul2(z2, pk2(0.5f, 0.5f))));
    ull res2 = add2(m2, y2);
    res2 = add2(res2, mul2(e2, pk2(0.693359375f, 0.693359375f)));
    up2(res2, ra, rb);
}

__device__ __forceinline__ float xla_log1p(float x) {
    float u = __fadd_rn(x, 1.0f);
    float w = __fmul_rn(xla_log(u), __fdiv_rn(x, __fsub_rn(u, 1.0f)));
    return (u == 1.0f) ? x : w;
}

__device__ __forceinline__ float xla_tanh(float x) {
    float xc = fminf(fmaxf(x, -7.90531110763549805f), 7.90531110763549805f);
    float x2 = __fmul_rn(xc, xc);
    float p = -2.76076847742355e-16f;
    p = __fmaf_rn(p, x2, 2.00018790482477e-13f);
    p = __fmaf_rn(p, x2, -8.60467152213735e-11f);
    p = __fmaf_rn(p, x2, 5.12229709037114e-08f);
    p = __fmaf_rn(p, x2, 1.48572235717979e-05f);
    p = __fmaf_rn(p, x2, 6.37261928875436e-04f);
    p = __fmaf_rn(p, x2, 4.89352455891786e-03f);
    float num = __fmul_rn(xc, p);
    float q = 1.19825839466702e-06f;
    q = __fmaf_rn(q, x2, 1.18534705686654e-04f);
    q = __fmaf_rn(q, x2, 2.26843463243900e-03f);
    q = __fmaf_rn(q, x2, 4.89352518554385e-03f);
    float r = __fdiv_rn(num, q);
    return (fabsf(x) < 0.0004f) ? x : r;
}

__device__ __forceinline__ float xla_sigmoid(float x) {
    return rcp_rn(__fadd_rn(1.0f, xla_exp(-x)));
}

__device__ __forceinline__ float xla_softplus(float x) {
    return __fadd_rn(fmaxf(x, 0.0f), xla_log1p(xla_exp(-fabsf(x))));
}

// packed pair softplus: per half bitwise identical to xla_softplus
__device__ __forceinline__ void xla_softplus2(float xa, float xb,
                                              float& ra, float& rb) {
    float ea, eb;
    xla_exp2(-fabsf(xa), -fabsf(xb), ea, eb);
    float ua = __fadd_rn(ea, 1.0f);
    float ub = __fadd_rn(eb, 1.0f);
    float la, lb;
    xla_log2(ua, ub, la, lb);
    float wa = __fmul_rn(la, __fdiv_rn(ea, __fsub_rn(ua, 1.0f)));
    float wb = __fmul_rn(lb, __fdiv_rn(eb, __fsub_rn(ub, 1.0f)));
    float l1a = (ua == 1.0f) ? ea : wa;
    float l1b = (ub == 1.0f) ? eb : wb;
    ra = __fadd_rn(fmaxf(xa, 0.0f), l1a);
    rb = __fadd_rn(fmaxf(xb, 0.0f), l1b);
}

// extra-bin logprob (cooperative pass): packs its two boundary sigmoids
__device__ __forceinline__ float bin_logprob_ex(int t, float m, float iv, float s) {
    if (t == 0) {
        float n0 = __fmul_rn(__fsub_rn(-0.9921875f, m), iv);
        return __fsub_rn(n0, xla_softplus(n0));
    }
    if (t == 255) {
        float n = __fmul_rn(__fsub_rn(0.9921875f, m), iv);
        return -xla_softplus(n);
    }
    float clo = __fadd_rn(__fmul_rn((float)t, 0.0078125f), -1.0f);
    float chi = __fadd_rn(__fmul_rn((float)(t + 1), 0.0078125f), -1.0f);
    float zhi = __fmul_rn(__fsub_rn(chi, m), iv);
    float zlo = __fmul_rn(__fsub_rn(clo, m), iv);
    float ehi, elo;
    xla_exp2(-zhi, -zlo, ehi, elo);
    float shi = rcp_rn(__fadd_rn(1.0f, ehi));
    float slo = rcp_rn(__fadd_rn(1.0f, elo));
    float pdf = __fsub_rn(shi, slo);
    if (pdf > 1e-5f) {
        return xla_log(fmaxf(pdf, 1e-12f));
    }
    float midc = __fadd_rn(__fmul_rn((float)(2 * t + 1), 0.00390625f), -1.0f);
    float mid = __fmul_rn(__fsub_rn(midc, m), iv);
    float mlp = __fsub_rn(__fsub_rn(mid, s), __fmul_rn(2.0f, xla_softplus(mid)));
    return __fsub_rn(mlp, LOG127_5);
}

__global__ __launch_bounds__(32 * NWARPS)
void mixlogistic_decode_kernel(const float* __restrict__ x,
                               const float* __restrict__ l,
                               const int* __restrict__ epsp,
                               float* __restrict__ out,
                               int npix)
{
    __shared__ float sLOG[NWARPS][KMIX];
    __shared__ float sLPI[NWARPS][KMIX];
    __shared__ float sM  [NWARPS][3][KMIX];
    __shared__ float sS  [NWARPS][3][KMIX];
    __shared__ float sINV[NWARPS][3][KMIX];
    __shared__ float sCF [NWARPS][3][KMIX];

    const int warp = threadIdx.x >> 5;
    const int lane = threadIdx.x & 31;
    const int P = blockIdx.x * NWARPS + warp;
    if (P >= npix) return;

    const int b  = P >> 10;
    const int hw = P & (HW - 1);

    for (int c = lane; c < 100; c += 32) {
        float v = l[(size_t)(b * 100 + c) * HW + hw];
        if (c < KMIX) {
            sLOG[warp][c] = v;
        } else {
            int cc  = (c - KMIX) / 30;
            int rem = (c - KMIX) % 30;
            int grp = rem / KMIX;
            int k   = rem % KMIX;
            if (grp == 0) {
                sM[warp][cc][k] = v;
            } else if (grp == 1) {
                float s = fmaxf(v, -7.0f);
                sS[warp][cc][k]   = s;
                sINV[warp][cc][k] = xla_exp(-s);
            } else {
                sCF[warp][cc][k] = xla_tanh(v);
            }
        }
    }
    __syncwarp();

    // cooperative log_softmax (exact fmax butterfly + parallel exp +
    // sequential ascending-k fold == XLA reduce rounding)
    {
        float lg = (lane < KMIX) ? sLOG[warp][lane] : -INFINITY;
        float mx = lg;
        #pragma unroll
        for (int off = 16; off; off >>= 1)
            mx = fmaxf(mx, __shfl_xor_sync(FULLMASK, mx, off));
        float e = xla_exp(__fsub_rn(lg, mx));
        float sum = 0.0f;
        #pragma unroll
        for (int k = 0; k < KMIX; k++)
            sum = __fadd_rn(sum, __shfl_sync(FULLMASK, e, k));
        float lsum = xla_log(sum);
        if (lane < KMIX)
            sLPI[warp][lane] = __fsub_rn(__fsub_rn(lg, mx), lsum);
    }
    __syncwarp();

    const int eps = epsp[0];
    float xr = 0.0f, xg = 0.0f;

    #pragma unroll
    for (int c = 0; c < 3; c++) {
        float xorig = x[(size_t)(b * 3 + c) * HW + hw];
        int r  = (int)(__fadd_rn(__fmul_rn(xorig, 127.5f), 127.5f));
        int lb = max(r - eps, 0);
        int ub = min(r + eps, 255);

        const int t0 = lb + lane;
        const bool v0 = (t0 <= ub);
        const float chi = __fadd_rn(__fmul_rn((float)(t0 + 1), 0.0078125f), -1.0f);

        // per-component params in lanes 0..9
        float mk = 0.0f, ivk = 0.0f, sk = 0.0f, lpik = 0.0f;
        if (lane < KMIX) {
            mk = sM[warp][c][lane];
            if (c == 1) {
                mk = __fadd_rn(mk, __fmul_rn(sCF[warp][0][lane], xr));
            } else if (c == 2) {
                mk = __fadd_rn(mk, __fmul_rn(sCF[warp][1][lane], xr));
                mk = __fadd_rn(mk, __fmul_rn(sCF[warp][2][lane], xg));
            }
            ivk  = sINV[warp][c][lane];
            sk   = sS[warp][c][lane];
            lpik = sLPI[warp][lane];
        }

        // lane-0 lower-boundary sigmoid per component (iff lb >= 1)
        float E = 0.0f;
        if (lb >= 1) {
            float cloLB = __fadd_rn(__fmul_rn((float)lb, 0.0078125f), -1.0f);
            E = xla_sigmoid(__fmul_rn(__fsub_rn(cloLB, mk), ivk));
        }

        // cooperative 33rd bin
        const int te = lb + 32;
        const bool haveExtra = (te <= ub);
        float lpe = -INFINITY;
        if (haveExtra && lane < KMIX) {
            lpe = __fadd_rn(bin_logprob_ex(te, mk, ivk, sk), lpik);
        }

        // ---- main 32 bins: interior formula for ALL lanes (boundary lanes
        //      produce discarded garbage, fixed up after the loop) ----
        const float midc = __fadd_rn(__fmul_rn((float)(2 * t0 + 1), 0.00390625f), -1.0f);
        float lp0[KMIX];
        #pragma unroll
        for (int j = 0; j < KMIX / 2; j++) {
            const int k0 = 2 * j, k1 = 2 * j + 1;
            float m0   = __shfl_sync(FULLMASK, mk,   k0);
            float m1   = __shfl_sync(FULLMASK, mk,   k1);
            float iv0  = __shfl_sync(FULLMASK, ivk,  k0);
            float iv1  = __shfl_sync(FULLMASK, ivk,  k1);
            float s0   = __shfl_sync(FULLMASK, sk,   k0);
            float s1   = __shfl_sync(FULLMASK, sk,   k1);
            float lpi0 = __shfl_sync(FULLMASK, lpik, k0);
            float lpi1 = __shfl_sync(FULLMASK, lpik, k1);
            float E0   = __shfl_sync(FULLMASK, E,    k0);
            float E1   = __shfl_sync(FULLMASK, E,    k1);

            float zhi0 = __fmul_rn(__fsub_rn(chi, m0), iv0);
            float zhi1 = __fmul_rn(__fsub_rn(chi, m1), iv1);
            float e0, e1;
            xla_exp2(-zhi0, -zhi1, e0, e1);
            float S0 = rcp_rn(__fadd_rn(1.0f, e0));
            float S1 = rcp_rn(__fadd_rn(1.0f, e1));
            float slo0 = __shfl_up_sync(FULLMASK, S0, 1);
            float slo1 = __shfl_up_sync(FULLMASK, S1, 1);
            if (lane == 0) { slo0 = E0; slo1 = E1; }

            float pdf0 = __fsub_rn(S0, slo0);
            float pdf1 = __fsub_rn(S1, slo1);
            float lg0, lg1;
            xla_log2(fmaxf(pdf0, 1e-12f), fmaxf(pdf1, 1e-12f), lg0, lg1);

            float lpA = lg0;
            float lpB = lg1;
            bool f0 = !(pdf0 > 1e-5f);
            bool f1 = !(pdf1 > 1e-5f);
            if (f0 || f1) {   // packed fallback: both halves computed
                float mid0 = __fmul_rn(__fsub_rn(midc, m0), iv0);
                float mid1 = __fmul_rn(__fsub_rn(midc, m1), iv1);
                float sp0, sp1;
                xla_softplus2(mid0, mid1, sp0, sp1);
                float a0 = __fsub_rn(__fsub_rn(__fsub_rn(mid0, s0),
                                               __fmul_rn(2.0f, sp0)), LOG127_5);
                float a1 = __fsub_rn(__fsub_rn(__fsub_rn(mid1, s1),
                                               __fmul_rn(2.0f, sp1)), LOG127_5);
                if (f0) lpA = a0;
                if (f1) lpB = a1;
            }
            lp0[k0] = __fadd_rn(lpA, lpi0);
            lp0[k1] = __fadd_rn(lpB, lpi1);
        }

        // ---- boundary fixups (warp-uniform; lanes 0..9 compute exact
        //      reference values per component, affected lane gathers) ----
        if (lb == 0) {        // lane 0's bin is t=0
            float bval = 0.0f;
            if (lane < KMIX) {
                float n0 = __fmul_rn(__fsub_rn(-0.9921875f, mk), ivk);
                bval = __fadd_rn(__fsub_rn(n0, xla_softplus(n0)), lpik);
            }
            #pragma unroll
            for (int k = 0; k < KMIX; k++) {
                float v = __shfl_sync(FULLMASK, bval, k);
                if (lane == 0) lp0[k] = v;
            }
        }
        if (lb >= 224) {      // lane (255-lb) has t=255
            const int lane255 = 255 - lb;
            float bval = 0.0f;
            if (lane < KMIX) {
                float n = __fmul_rn(__fsub_rn(0.9921875f, mk), ivk);
                bval = __fadd_rn(-xla_softplus(n), lpik);
            }
            #pragma unroll
            for (int k = 0; k < KMIX; k++) {
                float v = __shfl_sync(FULLMASK, bval, k);
                if (lane == lane255) lp0[k] = v;
            }
        }

        // per-bin logsumexp over k (sequential ascending k; packed sub + exps)
        float bv = -INFINITY;
        int   bt = 0x7FFFFFFF;
        if (v0) {
            float amax = lp0[0];
            #pragma unroll
            for (int k = 1; k < KMIX; k++) amax = fmaxf(amax, lp0[k]);
            ull am2 = pk2(amax, amax);
            float ex[KMIX];
            #pragma unroll
            for (int j = 0; j < KMIX / 2; j++) {
                float da, db;
                up2(add2(pk2(lp0[2 * j], lp0[2 * j + 1]), neg2(am2)), da, db);
                xla_exp2(da, db, ex[2 * j], ex[2 * j + 1]);
            }
            float sum = 0.0f;
            #pragma unroll
            for (int k = 0; k < KMIX; k++) sum = __fadd_rn(sum, ex[k]);
            bv = __fadd_rn(xla_log(sum), amax);
            bt = t0;
        }

        // warp argmax (first-index tie semantics)
        #pragma unroll
        for (int off = 16; off; off >>= 1) {
            float ov = __shfl_down_sync(FULLMASK, bv, off);
            int   ot = __shfl_down_sync(FULLMASK, bt, off);
            if (ov > bv || (ov == bv && ot < bt)) { bv = ov; bt = ot; }
        }

        // extra-bin logsumexp (uniform result; final compare on lane 0)
        if (haveExtra) {
            float amax = lpe;
            #pragma unroll
            for (int off = 16; off; off >>= 1)
                amax = fmaxf(amax, __shfl_xor_sync(FULLMASK, amax, off));
            float e = xla_exp(__fsub_rn(lpe, amax));
            float sum = 0.0f;
            #pragma unroll
            for (int k = 0; k < KMIX; k++)
                sum = __fadd_rn(sum, __shfl_sync(FULLMASK, e, k));
            float val = __fadd_rn(xla_log(sum), amax);
            if (lane == 0 && val > bv) { bv = val; bt = te; }
        }

        bt = __shfl_sync(FULLMASK, bt, 0);

        float outv = __fdiv_rn(__fsub_rn((float)bt, 127.5f), 127.5f);
        if (c == 0) xr = outv;
        else if (c == 1) xg = outv;

        if (lane == 0) {
            out[(size_t)(b * 3 + c) * HW + hw] = outv;
        }
    }
}

extern "C" void kernel_launch(void* const* d_in, const int* in_sizes, int n_in,
                              void* d_out, int out_size)
{
    const float* x   = (const float*)d_in[0];
    const float* l   = (const float*)d_in[1];
    const int*   eps = (const int*)d_in[2];
    float* out = (float*)d_out;

    int npix = in_sizes[0] / 3;
    int blocks = (npix + NWARPS - 1) / NWARPS;
    mixlogistic_decode_kernel<<<blocks, 32 * NWARPS>>>(x, l, eps, out, npix);
}

// round 15
// speedup vs baseline: 1.4872x; 1.0278x over previous
#include <cuda_runtime.h>

// Math replicates XLA:CPU cephes/Eigen lowering bit-for-bit (validated R5-R14).
// f32x2 packed ops do two independent IEEE-rn f32 ops -> bitwise identical per
// half. rcp.rn(x) == div.rn(1,x) bitwise (validated R10+).
// Params via shuffle-broadcast (smem float4 path regressed, R10). NWARPS=8.
// Boundary bins via post-loop warp-uniform fixups (R14 win).
// Fallback log fused into the main log2 via per-half input select (this round).

#define FULLMASK 0xFFFFFFFFu
#define NWARPS 8
#define KMIX 10
#define HW 1024
#define LOG127_5 4.8481163645984802f

typedef unsigned long long ull;

__device__ __forceinline__ ull pk2(float a, float b) {
    ull r; asm("mov.b64 %0,{%1,%2};" : "=l"(r) : "f"(a), "f"(b)); return r;
}
__device__ __forceinline__ void up2(ull p, float& a, float& b) {
    asm("mov.b64 {%0,%1},%2;" : "=f"(a), "=f"(b) : "l"(p));
}
__device__ __forceinline__ ull mul2(ull a, ull b) {
    ull r; asm("mul.rn.f32x2 %0,%1,%2;" : "=l"(r) : "l"(a), "l"(b)); return r;
}
__device__ __forceinline__ ull add2(ull a, ull b) {
    ull r; asm("add.rn.f32x2 %0,%1,%2;" : "=l"(r) : "l"(a), "l"(b)); return r;
}
__device__ __forceinline__ ull fma2(ull a, ull b, ull c) {
    ull r; asm("fma.rn.f32x2 %0,%1,%2,%3;" : "=l"(r) : "l"(a), "l"(b), "l"(c)); return r;
}
__device__ __forceinline__ ull neg2(ull a) { return a ^ 0x8000000080000000ull; }
__device__ __forceinline__ float rcp_rn(float x) {
    float r; asm("rcp.rn.f32 %0,%1;" : "=f"(r) : "f"(x)); return r;
}

// ---- scalar cephes exp/log (reference-bit-exact) ----
__device__ __forceinline__ float xla_exp(float x) {
    x = fminf(fmaxf(x, -88.3762626647949f), 88.3762626647950f);
    float fx = floorf(__fmaf_rn(x, 1.44269504088896341f, 0.5f));
    float r = __fsub_rn(x, __fmul_rn(fx, 0.693359375f));
    r = __fsub_rn(r, __fmul_rn(fx, -2.12194440e-4f));
    float z = __fmul_rn(r, r);
    float y = 1.9875691500E-4f;
    y = __fmaf_rn(y, r, 1.3981999507E-3f);
    y = __fmaf_rn(y, r, 8.3334519073E-3f);
    y = __fmaf_rn(y, r, 4.1665795894E-2f);
    y = __fmaf_rn(y, r, 1.6666665459E-1f);
    y = __fmaf_rn(y, r, 5.0000001201E-1f);
    y = __fmaf_rn(y, z, r);
    y = __fadd_rn(y, 1.0f);
    int n = (int)fx;
    return __fmul_rn(y, __int_as_float((n + 127) << 23));
}

__device__ __forceinline__ float xla_log(float x) {
    int bits = __float_as_int(x);
    float e = (float)((bits >> 23) - 126);
    float m = __int_as_float((bits & 0x007fffff) | 0x3f000000);
    if (m < 0.707106781186547524f) {
        e = __fsub_rn(e, 1.0f);
        m = __fadd_rn(__fsub_rn(m, 1.0f), m);
    } else {
        m = __fsub_rn(m, 1.0f);
    }
    float z = __fmul_rn(m, m);
    float y = 7.0376836292E-2f;
    y = __fmaf_rn(y, m, -1.1514610310E-1f);
    y = __fmaf_rn(y, m, 1.1676998740E-1f);
    y = __fmaf_rn(y, m, -1.2420140846E-1f);
    y = __fmaf_rn(y, m, 1.4249322787E-1f);
    y = __fmaf_rn(y, m, -1.6668057665E-1f);
    y = __fmaf_rn(y, m, 2.0000714765E-1f);
    y = __fmaf_rn(y, m, -2.4999993993E-1f);
    y = __fmaf_rn(y, m, 3.3333331174E-1f);
    y = __fmul_rn(y, m);
    y = __fmul_rn(y, z);
    y = __fadd_rn(y, __fmul_rn(e, -2.12194440e-4f));
    y = __fsub_rn(y, __fmul_rn(z, 0.5f));
    float res = __fadd_rn(m, y);
    res = __fadd_rn(res, __fmul_rn(e, 0.693359375f));
    return res;
}

// ---- packed-pair exp/log: bitwise identical per half to scalar versions ----
__device__ __forceinline__ void xla_exp2(float xa, float xb, float& ra, float& rb) {
    xa = fminf(fmaxf(xa, -88.3762626647949f), 88.3762626647950f);
    xb = fminf(fmaxf(xb, -88.3762626647949f), 88.3762626647950f);
    ull x2 = pk2(xa, xb);
    ull fx2 = fma2(x2, pk2(1.44269504088896341f, 1.44269504088896341f),
                   pk2(0.5f, 0.5f));
    float fa, fb; up2(fx2, fa, fb);
    fa = floorf(fa); fb = floorf(fb);
    fx2 = pk2(fa, fb);
    ull r2 = add2(x2, neg2(mul2(fx2, pk2(0.693359375f, 0.693359375f))));
    r2 = add2(r2, neg2(mul2(fx2, pk2(-2.12194440e-4f, -2.12194440e-4f))));
    ull z2 = mul2(r2, r2);
    ull y2 = pk2(1.9875691500E-4f, 1.9875691500E-4f);
    y2 = fma2(y2, r2, pk2(1.3981999507E-3f, 1.3981999507E-3f));
    y2 = fma2(y2, r2, pk2(8.3334519073E-3f, 8.3334519073E-3f));
    y2 = fma2(y2, r2, pk2(4.1665795894E-2f, 4.1665795894E-2f));
    y2 = fma2(y2, r2, pk2(1.6666665459E-1f, 1.6666665459E-1f));
    y2 = fma2(y2, r2, pk2(5.0000001201E-1f, 5.0000001201E-1f));
    y2 = fma2(y2, z2, r2);
    y2 = add2(y2, pk2(1.0f, 1.0f));
    float ya, yb; up2(y2, ya, yb);
    int na = (int)fa, nb = (int)fb;
    ra = __fmul_rn(ya, __int_as_float((na + 127) << 23));
    rb = __fmul_rn(yb, __int_as_float((nb + 127) << 23));
}

__device__ __forceinline__ void xla_log2(float xa, float xb, float& ra, float& rb) {
    int ba = __float_as_int(xa), bb = __float_as_int(xb);
    float ea = (float)((ba >> 23) - 126);
    float eb = (float)((bb >> 23) - 126);
    float ma = __int_as_float((ba & 0x007fffff) | 0x3f000000);
    float mb = __int_as_float((bb & 0x007fffff) | 0x3f000000);
    if (ma < 0.707106781186547524f) {
        ea = __fsub_rn(ea, 1.0f);
        ma = __fadd_rn(__fsub_rn(ma, 1.0f), ma);
    } else {
        ma = __fsub_rn(ma, 1.0f);
    }
    if (mb < 0.707106781186547524f) {
        eb = __fsub_rn(eb, 1.0f);
        mb = __fadd_rn(__fsub_rn(mb, 1.0f), mb);
    } else {
        mb = __fsub_rn(mb, 1.0f);
    }
    ull m2 = pk2(ma, mb);
    ull z2 = mul2(m2, m2);
    ull y2 = pk2(7.0376836292E-2f, 7.0376836292E-2f);
    y2 = fma2(y2, m2, pk2(-1.1514610310E-1f, -1.1514610310E-1f));
    y2 = fma2(y2, m2, pk2(1.1676998740E-1f, 1.1676998740E-1f));
    y2 = fma2(y2, m2, pk2(-1.2420140846E-1f, -1.2420140846E-1f));
    y2 = fma2(y2, m2, pk2(1.4249322787E-1f, 1.4249322787E-1f));
    y2 = fma2(y2, m2, pk2(-1.6668057665E-1f, -1.6668057665E-1f));
    y2 = fma2(y2, m2, pk2(2.0000714765E-1f, 2.0000714765E-1f));
    y2 = fma2(y2, m2, pk2(-2.4999993993E-1f, -2.4999993993E-1f));
    y2 = fma2(y2, m2, pk2(3.3333331174E-1f, 3.3333331174E-1f));
    y2 = mul2(y2, m2);
    y2 = mul2(y2, z2);
    ull e2 = pk2(ea, eb);
    y2 = add2(y2, mul2(e2, pk2(-2.12194440e-4f, -2.12194440e-4f)));
    y2 = add2(y2, neg2(mul2(z2, pk2(0.5f, 0.5f))));
    ull res2 = add2(m2, y2);
    res2 = add2(res2, mul2(e2, pk2(0.693359375f, 0.693359375f)));
    up2(res2, ra, rb);
}

__device__ __forceinline__ float xla_log1p(float x) {
    float u = __fadd_rn(x, 1.0f);
    float w = __fmul_rn(xla_log(u), __fdiv_rn(x, __fsub_rn(u, 1.0f)));
    return (u == 1.0f) ? x : w;
}

__device__ __forceinline__ float xla_tanh(float x) {
    float xc = fminf(fmaxf(x, -7.90531110763549805f), 7.90531110763549805f);
    float x2 = __fmul_rn(xc, xc);
    float p = -2.76076847742355e-16f;
    p = __fmaf_rn(p, x2, 2.00018790482477e-13f);
    p = __fmaf_rn(p, x2, -8.60467152213735e-11f);
    p = __fmaf_rn(p, x2, 5.12229709037114e-08f);
    p = __fmaf_rn(p, x2, 1.48572235717979e-05f);
    p = __fmaf_rn(p, x2, 6.37261928875436e-04f);
    p = __fmaf_rn(p, x2, 4.89352455891786e-03f);
    float num = __fmul_rn(xc, p);
    float q = 1.19825839466702e-06f;
    q = __fmaf_rn(q, x2, 1.18534705686654e-04f);
    q = __fmaf_rn(q, x2, 2.26843463243900e-03f);
    q = __fmaf_rn(q, x2, 4.89352518554385e-03f);
    float r = __fdiv_rn(num, q);
    return (fabsf(x) < 0.0004f) ? x : r;
}

__device__ __forceinline__ float xla_sigmoid(float x) {
    return rcp_rn(__fadd_rn(1.0f, xla_exp(-x)));
}

__device__ __forceinline__ float xla_softplus(float x) {
    return __fadd_rn(fmaxf(x, 0.0f), xla_log1p(xla_exp(-fabsf(x))));
}

// extra-bin logprob (cooperative pass): packs its two boundary sigmoids
__device__ __forceinline__ float bin_logprob_ex(int t, float m, float iv, float s) {
    if (t == 0) {
        float n0 = __fmul_rn(__fsub_rn(-0.9921875f, m), iv);
        return __fsub_rn(n0, xla_softplus(n0));
    }
    if (t == 255) {
        float n = __fmul_rn(__fsub_rn(0.9921875f, m), iv);
        return -xla_softplus(n);
    }
    float clo = __fadd_rn(__fmul_rn((float)t, 0.0078125f), -1.0f);
    float chi = __fadd_rn(__fmul_rn((float)(t + 1), 0.0078125f), -1.0f);
    float zhi = __fmul_rn(__fsub_rn(chi, m), iv);
    float zlo = __fmul_rn(__fsub_rn(clo, m), iv);
    float ehi, elo;
    xla_exp2(-zhi, -zlo, ehi, elo);
    float shi = rcp_rn(__fadd_rn(1.0f, ehi));
    float slo = rcp_rn(__fadd_rn(1.0f, elo));
    float pdf = __fsub_rn(shi, slo);
    if (pdf > 1e-5f) {
        return xla_log(fmaxf(pdf, 1e-12f));
    }
    float midc = __fadd_rn(__fmul_rn((float)(2 * t + 1), 0.00390625f), -1.0f);
    float mid = __fmul_rn(__fsub_rn(midc, m), iv);
    float mlp = __fsub_rn(__fsub_rn(mid, s), __fmul_rn(2.0f, xla_softplus(mid)));
    return __fsub_rn(mlp, LOG127_5);
}

__global__ __launch_bounds__(32 * NWARPS)
void mixlogistic_decode_kernel(const float* __restrict__ x,
                               const float* __restrict__ l,
                               const int* __restrict__ epsp,
                               float* __restrict__ out,
                               int npix)
{
    __shared__ float sLOG[NWARPS][KMIX];
    __shared__ float sLPI[NWARPS][KMIX];
    __shared__ float sM  [NWARPS][3][KMIX];
    __shared__ float sS  [NWARPS][3][KMIX];
    __shared__ float sINV[NWARPS][3][KMIX];
    __shared__ float sCF [NWARPS][3][KMIX];

    const int warp = threadIdx.x >> 5;
    const int lane = threadIdx.x & 31;
    const int P = blockIdx.x * NWARPS + warp;
    if (P >= npix) return;

    const int b  = P >> 10;
    const int hw = P & (HW - 1);

    for (int c = lane; c < 100; c += 32) {
        float v = l[(size_t)(b * 100 + c) * HW + hw];
        if (c < KMIX) {
            sLOG[warp][c] = v;
        } else {
            int cc  = (c - KMIX) / 30;
            int rem = (c - KMIX) % 30;
            int grp = rem / KMIX;
            int k   = rem % KMIX;
            if (grp == 0) {
                sM[warp][cc][k] = v;
            } else if (grp == 1) {
                float s = fmaxf(v, -7.0f);
                sS[warp][cc][k]   = s;
                sINV[warp][cc][k] = xla_exp(-s);
            } else {
                sCF[warp][cc][k] = xla_tanh(v);
            }
        }
    }
    __syncwarp();

    // cooperative log_softmax (exact fmax butterfly + parallel exp +
    // sequential ascending-k fold == XLA reduce rounding)
    {
        float lg = (lane < KMIX) ? sLOG[warp][lane] : -INFINITY;
        float mx = lg;
        #pragma unroll
        for (int off = 16; off; off >>= 1)
            mx = fmaxf(mx, __shfl_xor_sync(FULLMASK, mx, off));
        float e = xla_exp(__fsub_rn(lg, mx));
        float sum = 0.0f;
        #pragma unroll
        for (int k = 0; k < KMIX; k++)
            sum = __fadd_rn(sum, __shfl_sync(FULLMASK, e, k));
        float lsum = xla_log(sum);
        if (lane < KMIX)
            sLPI[warp][lane] = __fsub_rn(__fsub_rn(lg, mx), lsum);
    }
    __syncwarp();

    const int eps = epsp[0];
    float xr = 0.0f, xg = 0.0f;

    #pragma unroll
    for (int c = 0; c < 3; c++) {
        float xorig = x[(size_t)(b * 3 + c) * HW + hw];
        int r  = (int)(__fadd_rn(__fmul_rn(xorig, 127.5f), 127.5f));
        int lb = max(r - eps, 0);
        int ub = min(r + eps, 255);

        const int t0 = lb + lane;
        const bool v0 = (t0 <= ub);
        const float chi = __fadd_rn(__fmul_rn((float)(t0 + 1), 0.0078125f), -1.0f);

        // per-component params in lanes 0..9
        float mk = 0.0f, ivk = 0.0f, sk = 0.0f, lpik = 0.0f;
        if (lane < KMIX) {
            mk = sM[warp][c][lane];
            if (c == 1) {
                mk = __fadd_rn(mk, __fmul_rn(sCF[warp][0][lane], xr));
            } else if (c == 2) {
                mk = __fadd_rn(mk, __fmul_rn(sCF[warp][1][lane], xr));
                mk = __fadd_rn(mk, __fmul_rn(sCF[warp][2][lane], xg));
            }
            ivk  = sINV[warp][c][lane];
            sk   = sS[warp][c][lane];
            lpik = sLPI[warp][lane];
        }

        // lane-0 lower-boundary sigmoid per component (iff lb >= 1)
        float E = 0.0f;
        if (lb >= 1) {
            float cloLB = __fadd_rn(__fmul_rn((float)lb, 0.0078125f), -1.0f);
            E = xla_sigmoid(__fmul_rn(__fsub_rn(cloLB, mk), ivk));
        }

        // cooperative 33rd bin
        const int te = lb + 32;
        const bool haveExtra = (te <= ub);
        float lpe = -INFINITY;
        if (haveExtra && lane < KMIX) {
            lpe = __fadd_rn(bin_logprob_ex(te, mk, ivk, sk), lpik);
        }

        // ---- main 32 bins: interior formula for ALL lanes; fallback log fused
        //      into the main log2 via per-half input selection ----
        const float midc = __fadd_rn(__fmul_rn((float)(2 * t0 + 1), 0.00390625f), -1.0f);
        float lp0[KMIX];
        #pragma unroll
        for (int j = 0; j < KMIX / 2; j++) {
            const int k0 = 2 * j, k1 = 2 * j + 1;
            float m0   = __shfl_sync(FULLMASK, mk,   k0);
            float m1   = __shfl_sync(FULLMASK, mk,   k1);
            float iv0  = __shfl_sync(FULLMASK, ivk,  k0);
            float iv1  = __shfl_sync(FULLMASK, ivk,  k1);
            float lpi0 = __shfl_sync(FULLMASK, lpik, k0);
            float lpi1 = __shfl_sync(FULLMASK, lpik, k1);
            float E0   = __shfl_sync(FULLMASK, E,    k0);
            float E1   = __shfl_sync(FULLMASK, E,    k1);

            float zhi0 = __fmul_rn(__fsub_rn(chi, m0), iv0);
            float zhi1 = __fmul_rn(__fsub_rn(chi, m1), iv1);
            float e0, e1;
            xla_exp2(-zhi0, -zhi1, e0, e1);
            float S0 = rcp_rn(__fadd_rn(1.0f, e0));
            float S1 = rcp_rn(__fadd_rn(1.0f, e1));
            float slo0 = __shfl_up_sync(FULLMASK, S0, 1);
            float slo1 = __shfl_up_sync(FULLMASK, S1, 1);
            if (lane == 0) { slo0 = E0; slo1 = E1; }

            float pdf0 = __fsub_rn(S0, slo0);
            float pdf1 = __fsub_rn(S1, slo1);
            bool f0 = !(pdf0 > 1e-5f);
            bool f1 = !(pdf1 > 1e-5f);

            // warp-uniform fallback prep (ballot makes the guard uniform so the
            // s-shuffles inside stay converged)
            unsigned bal = __ballot_sync(FULLMASK, f0 || f1);
            float lin0 = fmaxf(pdf0, 1e-12f);
            float lin1 = fmaxf(pdf1, 1e-12f);
            float mid0 = 0.0f, mid1 = 0.0f, es0 = 0.0f, es1 = 0.0f;
            float u0 = 0.0f, u1 = 0.0f, s0 = 0.0f, s1 = 0.0f;
            if (bal) {
                s0 = __shfl_sync(FULLMASK, sk, k0);
                s1 = __shfl_sync(FULLMASK, sk, k1);
                mid0 = __fmul_rn(__fsub_rn(midc, m0), iv0);
                mid1 = __fmul_rn(__fsub_rn(midc, m1), iv1);
                xla_exp2(-fabsf(mid0), -fabsf(mid1), es0, es1);
                u0 = __fadd_rn(es0, 1.0f);
                u1 = __fadd_rn(es1, 1.0f);
                if (f0) lin0 = u0;
                if (f1) lin1 = u1;
            }

            float L0, L1;
            xla_log2(lin0, lin1, L0, L1);   // one log serves both purposes

            float lpA = L0;
            float lpB = L1;
            if (bal) {
                if (f0) {
                    float w  = __fmul_rn(L0, __fdiv_rn(es0, __fsub_rn(u0, 1.0f)));
                    float l1 = (u0 == 1.0f) ? es0 : w;
                    float sp = __fadd_rn(fmaxf(mid0, 0.0f), l1);
                    lpA = __fsub_rn(__fsub_rn(__fsub_rn(mid0, s0),
                                              __fmul_rn(2.0f, sp)), LOG127_5);
                }
                if (f1) {
                    float w  = __fmul_rn(L1, __fdiv_rn(es1, __fsub_rn(u1, 1.0f)));
                    float l1 = (u1 == 1.0f) ? es1 : w;
                    float sp = __fadd_rn(fmaxf(mid1, 0.0f), l1);
                    lpB = __fsub_rn(__fsub_rn(__fsub_rn(mid1, s1),
                                              __fmul_rn(2.0f, sp)), LOG127_5);
                }
            }
            lp0[k0] = __fadd_rn(lpA, lpi0);
            lp0[k1] = __fadd_rn(lpB, lpi1);
        }

        // ---- boundary fixups (warp-uniform; lanes 0..9 compute exact
        //      reference values per component, affected lane gathers) ----
        if (lb == 0) {        // lane 0's bin is t=0
            float bval = 0.0f;
            if (lane < KMIX) {
                float n0 = __fmul_rn(__fsub_rn(-0.9921875f, mk), ivk);
                bval = __fadd_rn(__fsub_rn(n0, xla_softplus(n0)), lpik);
            }
            #pragma unroll
            for (int k = 0; k < KMIX; k++) {
                float v = __shfl_sync(FULLMASK, bval, k);
                if (lane == 0) lp0[k] = v;
            }
        }
        if (lb >= 224) {      // lane (255-lb) has t=255
            const int lane255 = 255 - lb;
            float bval = 0.0f;
            if (lane < KMIX) {
                float n = __fmul_rn(__fsub_rn(0.9921875f, mk), ivk);
                bval = __fadd_rn(-xla_softplus(n), lpik);
            }
            #pragma unroll
            for (int k = 0; k < KMIX; k++) {
                float v = __shfl_sync(FULLMASK, bval, k);
                if (lane == lane255) lp0[k] = v;
            }
        }

        // per-bin logsumexp over k (sequential ascending k; packed sub + exps)
        float bv = -INFINITY;
        int   bt = 0x7FFFFFFF;
        if (v0) {
            float amax = lp0[0];
            #pragma unroll
            for (int k = 1; k < KMIX; k++) amax = fmaxf(amax, lp0[k]);
            ull am2 = pk2(amax, amax);
            float ex[KMIX];
            #pragma unroll
            for (int j = 0; j < KMIX / 2; j++) {
                float da, db;
                up2(add2(pk2(lp0[2 * j], lp0[2 * j + 1]), neg2(am2)), da, db);
                xla_exp2(da, db, ex[2 * j], ex[2 * j + 1]);
            }
            float sum = 0.0f;
            #pragma unroll
            for (int k = 0; k < KMIX; k++) sum = __fadd_rn(sum, ex[k]);
            bv = __fadd_rn(xla_log(sum), amax);
            bt = t0;
        }

        // warp argmax (first-index tie semantics)
        #pragma unroll
        for (int off = 16; off; off >>= 1) {
            float ov = __shfl_down_sync(FULLMASK, bv, off);
            int   ot = __shfl_down_sync(FULLMASK, bt, off);
            if (ov > bv || (ov == bv && ot < bt)) { bv = ov; bt = ot; }
        }

        // extra-bin logsumexp (uniform result; final compare on lane 0)
        if (haveExtra) {
            float amax = lpe;
            #pragma unroll
            for (int off = 16; off; off >>= 1)
                amax = fmaxf(amax, __shfl_xor_sync(FULLMASK, amax, off));
            float e = xla_exp(__fsub_rn(lpe, amax));
            float sum = 0.0f;
            #pragma unroll
            for (int k = 0; k < KMIX; k++)
                sum = __fadd_rn(sum, __shfl_sync(FULLMASK, e, k));
            float val = __fadd_rn(xla_log(sum), amax);
            if (lane == 0 && val > bv) { bv = val; bt = te; }
        }

        bt = __shfl_sync(FULLMASK, bt, 0);

        float outv = __fdiv_rn(__fsub_rn((float)bt, 127.5f), 127.5f);
        if (c == 0) xr = outv;
        else if (c == 1) xg = outv;

        if (lane == 0) {
            out[(size_t)(b * 3 + c) * HW + hw] = outv;
        }
    }
}

extern "C" void kernel_launch(void* const* d_in, const int* in_sizes, int n_in,
                              void* d_out, int out_size)
{
    const float* x   = (const float*)d_in[0];
    const float* l   = (const float*)d_in[1];
    const int*   eps = (const int*)d_in[2];
    float* out = (float*)d_out;

    int npix = in_sizes[0] / 3;
    int blocks = (npix + NWARPS - 1) / NWARPS;
    mixlogistic_decode_kernel<<<blocks, 32 * NWARPS>>>(x, l, eps, out, npix);
}

// round 16
// speedup vs baseline: 1.4897x; 1.0017x over previous
#include <cuda_runtime.h>

// Math replicates XLA:CPU cephes/Eigen lowering bit-for-bit (validated R5-R15).
// f32x2 packed ops do two independent IEEE-rn f32 ops -> bitwise identical per
// half. rcp.rn(x) == div.rn(1,x) bitwise (validated R10+).
// Params via shuffle-broadcast (smem float4 path regressed, R10). NWARPS=8.
// Boundary bins via post-loop warp-uniform fixups (R14). Fallback log fused
// into main log2 (R15). This round: E + extra-bin sigmoid exps packed into one
// exp2; dead extra-bin branches removed.

#define FULLMASK 0xFFFFFFFFu
#define NWARPS 8
#define KMIX 10
#define HW 1024
#define LOG127_5 4.8481163645984802f

typedef unsigned long long ull;

__device__ __forceinline__ ull pk2(float a, float b) {
    ull r; asm("mov.b64 %0,{%1,%2};" : "=l"(r) : "f"(a), "f"(b)); return r;
}
__device__ __forceinline__ void up2(ull p, float& a, float& b) {
    asm("mov.b64 {%0,%1},%2;" : "=f"(a), "=f"(b) : "l"(p));
}
__device__ __forceinline__ ull mul2(ull a, ull b) {
    ull r; asm("mul.rn.f32x2 %0,%1,%2;" : "=l"(r) : "l"(a), "l"(b)); return r;
}
__device__ __forceinline__ ull add2(ull a, ull b) {
    ull r; asm("add.rn.f32x2 %0,%1,%2;" : "=l"(r) : "l"(a), "l"(b)); return r;
}
__device__ __forceinline__ ull fma2(ull a, ull b, ull c) {
    ull r; asm("fma.rn.f32x2 %0,%1,%2,%3;" : "=l"(r) : "l"(a), "l"(b), "l"(c)); return r;
}
__device__ __forceinline__ ull neg2(ull a) { return a ^ 0x8000000080000000ull; }
__device__ __forceinline__ float rcp_rn(float x) {
    float r; asm("rcp.rn.f32 %0,%1;" : "=f"(r) : "f"(x)); return r;
}

// ---- scalar cephes exp/log (reference-bit-exact) ----
__device__ __forceinline__ float xla_exp(float x) {
    x = fminf(fmaxf(x, -88.3762626647949f), 88.3762626647950f);
    float fx = floorf(__fmaf_rn(x, 1.44269504088896341f, 0.5f));
    float r = __fsub_rn(x, __fmul_rn(fx, 0.693359375f));
    r = __fsub_rn(r, __fmul_rn(fx, -2.12194440e-4f));
    float z = __fmul_rn(r, r);
    float y = 1.9875691500E-4f;
    y = __fmaf_rn(y, r, 1.3981999507E-3f);
    y = __fmaf_rn(y, r, 8.3334519073E-3f);
    y = __fmaf_rn(y, r, 4.1665795894E-2f);
    y = __fmaf_rn(y, r, 1.6666665459E-1f);
    y = __fmaf_rn(y, r, 5.0000001201E-1f);
    y = __fmaf_rn(y, z, r);
    y = __fadd_rn(y, 1.0f);
    int n = (int)fx;
    return __fmul_rn(y, __int_as_float((n + 127) << 23));
}

__device__ __forceinline__ float xla_log(float x) {
    int bits = __float_as_int(x);
    float e = (float)((bits >> 23) - 126);
    float m = __int_as_float((bits & 0x007fffff) | 0x3f000000);
    if (m < 0.707106781186547524f) {
        e = __fsub_rn(e, 1.0f);
        m = __fadd_rn(__fsub_rn(m, 1.0f), m);
    } else {
        m = __fsub_rn(m, 1.0f);
    }
    float z = __fmul_rn(m, m);
    float y = 7.0376836292E-2f;
    y = __fmaf_rn(y, m, -1.1514610310E-1f);
    y = __fmaf_rn(y, m, 1.1676998740E-1f);
    y = __fmaf_rn(y, m, -1.2420140846E-1f);
    y = __fmaf_rn(y, m, 1.4249322787E-1f);
    y = __fmaf_rn(y, m, -1.6668057665E-1f);
    y = __fmaf_rn(y, m, 2.0000714765E-1f);
    y = __fmaf_rn(y, m, -2.4999993993E-1f);
    y = __fmaf_rn(y, m, 3.3333331174E-1f);
    y = __fmul_rn(y, m);
    y = __fmul_rn(y, z);
    y = __fadd_rn(y, __fmul_rn(e, -2.12194440e-4f));
    y = __fsub_rn(y, __fmul_rn(z, 0.5f));
    float res = __fadd_rn(m, y);
    res = __fadd_rn(res, __fmul_rn(e, 0.693359375f));
    return res;
}

// ---- packed-pair exp/log: bitwise identical per half to scalar versions ----
__device__ __forceinline__ void xla_exp2(float xa, float xb, float& ra, float& rb) {
    xa = fminf(fmaxf(xa, -88.3762626647949f), 88.3762626647950f);
    xb = fminf(fmaxf(xb, -88.3762626647949f), 88.3762626647950f);
    ull x2 = pk2(xa, xb);
    ull fx2 = fma2(x2, pk2(1.44269504088896341f, 1.44269504088896341f),
                   pk2(0.5f, 0.5f));
    float fa, fb; up2(fx2, fa, fb);
    fa = floorf(fa); fb = floorf(fb);
    fx2 = pk2(fa, fb);
    ull r2 = add2(x2, neg2(mul2(fx2, pk2(0.693359375f, 0.693359375f))));
    r2 = add2(r2, neg2(mul2(fx2, pk2(-2.12194440e-4f, -2.12194440e-4f))));
    ull z2 = mul2(r2, r2);
    ull y2 = pk2(1.9875691500E-4f, 1.9875691500E-4f);
    y2 = fma2(y2, r2, pk2(1.3981999507E-3f, 1.3981999507E-3f));
    y2 = fma2(y2, r2, pk2(8.3334519073E-3f, 8.3334519073E-3f));
    y2 = fma2(y2, r2, pk2(4.1665795894E-2f, 4.1665795894E-2f));
    y2 = fma2(y2, r2, pk2(1.6666665459E-1f, 1.6666665459E-1f));
    y2 = fma2(y2, r2, pk2(5.0000001201E-1f, 5.0000001201E-1f));
    y2 = fma2(y2, z2, r2);
    y2 = add2(y2, pk2(1.0f, 1.0f));
    float ya, yb; up2(y2, ya, yb);
    int na = (int)fa, nb = (int)fb;
    ra = __fmul_rn(ya, __int_as_float((na + 127) << 23));
    rb = __fmul_rn(yb, __int_as_float((nb + 127) << 23));
}

__device__ __forceinline__ void xla_log2(float xa, float xb, float& ra, float& rb) {
    int ba = __float_as_int(xa), bb = __float_as_int(xb);
    float ea = (float)((ba >> 23) - 126);
    float eb = (float)((bb >> 23) - 126);
    float ma = __int_as_float((ba & 0x007fffff) | 0x3f000000);
    float mb = __int_as_float((bb & 0x007fffff) | 0x3f000000);
    if (ma < 0.707106781186547524f) {
        ea = __fsub_rn(ea, 1.0f);
        ma = __fadd_rn(__fsub_rn(ma, 1.0f), ma);
    } else {
        ma = __fsub_rn(ma, 1.0f);
    }
    if (mb < 0.707106781186547524f) {
        eb = __fsub_rn(eb, 1.0f);
        mb = __fadd_rn(__fsub_rn(mb, 1.0f), mb);
    } else {
        mb = __fsub_rn(mb, 1.0f);
    }
    ull m2 = pk2(ma, mb);
    ull z2 = mul2(m2, m2);
    ull y2 = pk2(7.0376836292E-2f, 7.0376836292E-2f);
    y2 = fma2(y2, m2, pk2(-1.1514610310E-1f, -1.1514610310E-1f));
    y2 = fma2(y2, m2, pk2(1.1676998740E-1f, 1.1676998740E-1f));
    y2 = fma2(y2, m2, pk2(-1.2420140846E-1f, -1.2420140846E-1f));
    y2 = fma2(y2, m2, pk2(1.4249322787E-1f, 1.4249322787E-1f));
    y2 = fma2(y2, m2, pk2(-1.6668057665E-1f, -1.6668057665E-1f));
    y2 = fma2(y2, m2, pk2(2.0000714765E-1f, 2.0000714765E-1f));
    y2 = fma2(y2, m2, pk2(-2.4999993993E-1f, -2.4999993993E-1f));
    y2 = fma2(y2, m2, pk2(3.3333331174E-1f, 3.3333331174E-1f));
    y2 = mul2(y2, m2);
    y2 = mul2(y2, z2);
    ull e2 = pk2(ea, eb);
    y2 = add2(y2, mul2(e2, pk2(-2.12194440e-4f, -2.12194440e-4f)));
    y2 = add2(y2, neg2(mul2(z2, pk2(0.5f, 0.5f))));
    ull res2 = add2(m2, y2);
    res2 = add2(res2, mul2(e2, pk2(0.693359375f, 0.693359375f)));
    up2(res2, ra, rb);
}

__device__ __forceinline__ float xla_log1p(float x) {
    float u = __fadd_rn(x, 1.0f);
    float w = __fmul_rn(xla_log(u), __fdiv_rn(x, __fsub_rn(u, 1.0f)));
    return (u == 1.0f) ? x : w;
}

__device__ __forceinline__ float xla_tanh(float x) {
    float xc = fminf(fmaxf(x, -7.90531110763549805f), 7.90531110763549805f);
    float x2 = __fmul_rn(xc, xc);
    float p = -2.76076847742355e-16f;
    p = __fmaf_rn(p, x2, 2.00018790482477e-13f);
    p = __fmaf_rn(p, x2, -8.60467152213735e-11f);
    p = __fmaf_rn(p, x2, 5.12229709037114e-08f);
    p = __fmaf_rn(p, x2, 1.48572235717979e-05f);
    p = __fmaf_rn(p, x2, 6.37261928875436e-04f);
    p = __fmaf_rn(p, x2, 4.89352455891786e-03f);
    float num = __fmul_rn(xc, p);
    float q = 1.19825839466702e-06f;
    q = __fmaf_rn(q, x2, 1.18534705686654e-04f);
    q = __fmaf_rn(q, x2, 2.26843463243900e-03f);
    q = __fmaf_rn(q, x2, 4.89352518554385e-03f);
    float r = __fdiv_rn(num, q);
    return (fabsf(x) < 0.0004f) ? x : r;
}

__device__ __forceinline__ float xla_softplus(float x) {
    return __fadd_rn(fmaxf(x, 0.0f), xla_log1p(xla_exp(-fabsf(x))));
}

__global__ __launch_bounds__(32 * NWARPS)
void mixlogistic_decode_kernel(const float* __restrict__ x,
                               const float* __restrict__ l,
                               const int* __restrict__ epsp,
                               float* __restrict__ out,
                               int npix)
{
    __shared__ float sLOG[NWARPS][KMIX];
    __shared__ float sLPI[NWARPS][KMIX];
    __shared__ float sM  [NWARPS][3][KMIX];
    __shared__ float sS  [NWARPS][3][KMIX];
    __shared__ float sINV[NWARPS][3][KMIX];
    __shared__ float sCF [NWARPS][3][KMIX];

    const int warp = threadIdx.x >> 5;
    const int lane = threadIdx.x & 31;
    const int P = blockIdx.x * NWARPS + warp;
    if (P >= npix) return;

    const int b  = P >> 10;
    const int hw = P & (HW - 1);

    for (int c = lane; c < 100; c += 32) {
        float v = l[(size_t)(b * 100 + c) * HW + hw];
        if (c < KMIX) {
            sLOG[warp][c] = v;
        } else {
            int cc  = (c - KMIX) / 30;
            int rem = (c - KMIX) % 30;
            int grp = rem / KMIX;
            int k   = rem % KMIX;
            if (grp == 0) {
                sM[warp][cc][k] = v;
            } else if (grp == 1) {
                float s = fmaxf(v, -7.0f);
                sS[warp][cc][k]   = s;
                sINV[warp][cc][k] = xla_exp(-s);
            } else {
                sCF[warp][cc][k] = xla_tanh(v);
            }
        }
    }
    __syncwarp();

    // cooperative log_softmax (exact fmax butterfly + parallel exp +
    // sequential ascending-k fold == XLA reduce rounding)
    {
        float lg = (lane < KMIX) ? sLOG[warp][lane] : -INFINITY;
        float mx = lg;
        #pragma unroll
        for (int off = 16; off; off >>= 1)
            mx = fmaxf(mx, __shfl_xor_sync(FULLMASK, mx, off));
        float e = xla_exp(__fsub_rn(lg, mx));
        float sum = 0.0f;
        #pragma unroll
        for (int k = 0; k < KMIX; k++)
            sum = __fadd_rn(sum, __shfl_sync(FULLMASK, e, k));
        float lsum = xla_log(sum);
        if (lane < KMIX)
            sLPI[warp][lane] = __fsub_rn(__fsub_rn(lg, mx), lsum);
    }
    __syncwarp();

    const int eps = epsp[0];
    float xr = 0.0f, xg = 0.0f;

    #pragma unroll
    for (int c = 0; c < 3; c++) {
        float xorig = x[(size_t)(b * 3 + c) * HW + hw];
        int r  = (int)(__fadd_rn(__fmul_rn(xorig, 127.5f), 127.5f));
        int lb = max(r - eps, 0);
        int ub = min(r + eps, 255);

        const int t0 = lb + lane;
        const bool v0 = (t0 <= ub);
        const float chi = __fadd_rn(__fmul_rn((float)(t0 + 1), 0.0078125f), -1.0f);

        const int te = lb + 32;
        const bool haveExtra = (te <= ub);

        // per-component params + boundary/extra-bin work, lanes 0..9
        float mk = 0.0f, ivk = 0.0f, sk = 0.0f, lpik = 0.0f;
        float E = 0.0f, lpe = -INFINITY;
        if (lane < KMIX) {
            mk = sM[warp][c][lane];
            if (c == 1) {
                mk = __fadd_rn(mk, __fmul_rn(sCF[warp][0][lane], xr));
            } else if (c == 2) {
                mk = __fadd_rn(mk, __fmul_rn(sCF[warp][1][lane], xr));
                mk = __fadd_rn(mk, __fmul_rn(sCF[warp][2][lane], xg));
            }
            ivk  = sINV[warp][c][lane];
            sk   = sS[warp][c][lane];
            lpik = sLPI[warp][lane];

            // E = sigmoid at colors[lb] (unused if lb==0: lane-0 fixup wins);
            // extra-bin lower boundary = sigmoid at colors[te]. One packed exp.
            float cE  = __fadd_rn(__fmul_rn((float)lb, 0.0078125f), -1.0f);
            float cLo = __fadd_rn(__fmul_rn((float)te, 0.0078125f), -1.0f);
            float zE  = __fmul_rn(__fsub_rn(cE,  mk), ivk);
            float zLo = __fmul_rn(__fsub_rn(cLo, mk), ivk);
            float eE, eLo;
            xla_exp2(-zE, -zLo, eE, eLo);
            E = rcp_rn(__fadd_rn(1.0f, eE));

            if (haveExtra) {            // warp-uniform within lane<KMIX region
                if (te == 255) {        // rare (lb==223): exact -softplus path
                    lpe = __fadd_rn(-xla_softplus(zLo), lpik);
                } else {
                    float cHi = __fadd_rn(__fmul_rn((float)(te + 1), 0.0078125f), -1.0f);
                    float zHi = __fmul_rn(__fsub_rn(cHi, mk), ivk);
                    float eHi = xla_exp(-zHi);
                    float shi = rcp_rn(__fadd_rn(1.0f, eHi));
                    float slo = rcp_rn(__fadd_rn(1.0f, eLo));
                    float pdf = __fsub_rn(shi, slo);
                    float core;
                    if (pdf > 1e-5f) {
                        core = xla_log(fmaxf(pdf, 1e-12f));
                    } else {
                        float mc  = __fadd_rn(__fmul_rn((float)(2 * te + 1), 0.00390625f), -1.0f);
                        float mid = __fmul_rn(__fsub_rn(mc, mk), ivk);
                        core = __fsub_rn(__fsub_rn(__fsub_rn(mid, sk),
                                         __fmul_rn(2.0f, xla_softplus(mid))), LOG127_5);
                    }
                    lpe = __fadd_rn(core, lpik);
                }
            }
        }

        // ---- main 32 bins: interior formula for ALL lanes; fallback log fused
        //      into the main log2 via per-half input selection ----
        const float midc = __fadd_rn(__fmul_rn((float)(2 * t0 + 1), 0.00390625f), -1.0f);
        float lp0[KMIX];
        #pragma unroll
        for (int j = 0; j < KMIX / 2; j++) {
            const int k0 = 2 * j, k1 = 2 * j + 1;
            float m0   = __shfl_sync(FULLMASK, mk,   k0);
            float m1   = __shfl_sync(FULLMASK, mk,   k1);
            float iv0  = __shfl_sync(FULLMASK, ivk,  k0);
            float iv1  = __shfl_sync(FULLMASK, ivk,  k1);
            float lpi0 = __shfl_sync(FULLMASK, lpik, k0);
            float lpi1 = __shfl_sync(FULLMASK, lpik, k1);
            float E0   = __shfl_sync(FULLMASK, E,    k0);
            float E1   = __shfl_sync(FULLMASK, E,    k1);

            float zhi0 = __fmul_rn(__fsub_rn(chi, m0), iv0);
            float zhi1 = __fmul_rn(__fsub_rn(chi, m1), iv1);
            float e0, e1;
            xla_exp2(-zhi0, -zhi1, e0, e1);
            float S0 = rcp_rn(__fadd_rn(1.0f, e0));
            float S1 = rcp_rn(__fadd_rn(1.0f, e1));
            float slo0 = __shfl_up_sync(FULLMASK, S0, 1);
            float slo1 = __shfl_up_sync(FULLMASK, S1, 1);
            if (lane == 0) { slo0 = E0; slo1 = E1; }

            float pdf0 = __fsub_rn(S0, slo0);
            float pdf1 = __fsub_rn(S1, slo1);
            bool f0 = !(pdf0 > 1e-5f);
            bool f1 = !(pdf1 > 1e-5f);

            unsigned bal = __ballot_sync(FULLMASK, f0 || f1);
            float lin0 = fmaxf(pdf0, 1e-12f);
            float lin1 = fmaxf(pdf1, 1e-12f);
            float mid0 = 0.0f, mid1 = 0.0f, es0 = 0.0f, es1 = 0.0f;
            float u0 = 0.0f, u1 = 0.0f, s0 = 0.0f, s1 = 0.0f;
            if (bal) {
                s0 = __shfl_sync(FULLMASK, sk, k0);
                s1 = __shfl_sync(FULLMASK, sk, k1);
                mid0 = __fmul_rn(__fsub_rn(midc, m0), iv0);
                mid1 = __fmul_rn(__fsub_rn(midc, m1), iv1);
                xla_exp2(-fabsf(mid0), -fabsf(mid1), es0, es1);
                u0 = __fadd_rn(es0, 1.0f);
                u1 = __fadd_rn(es1, 1.0f);
                if (f0) lin0 = u0;
                if (f1) lin1 = u1;
            }

            float L0, L1;
            xla_log2(lin0, lin1, L0, L1);   // one log serves both purposes

            float lpA = L0;
            float lpB = L1;
            if (bal) {
                if (f0) {
                    float w  = __fmul_rn(L0, __fdiv_rn(es0, __fsub_rn(u0, 1.0f)));
                    float l1 = (u0 == 1.0f) ? es0 : w;
                    float sp = __fadd_rn(fmaxf(mid0, 0.0f), l1);
                    lpA = __fsub_rn(__fsub_rn(__fsub_rn(mid0, s0),
                                              __fmul_rn(2.0f, sp)), LOG127_5);
                }
                if (f1) {
                    float w  = __fmul_rn(L1, __fdiv_rn(es1, __fsub_rn(u1, 1.0f)));
                    float l1 = (u1 == 1.0f) ? es1 : w;
                    float sp = __fadd_rn(fmaxf(mid1, 0.0f), l1);
                    lpB = __fsub_rn(__fsub_rn(__fsub_rn(mid1, s1),
                                              __fmul_rn(2.0f, sp)), LOG127_5);
                }
            }
            lp0[k0] = __fadd_rn(lpA, lpi0);
            lp0[k1] = __fadd_rn(lpB, lpi1);
        }

        // ---- boundary fixups (warp-uniform; lanes 0..9 compute exact
        //      reference values per component, affected lane gathers) ----
        if (lb == 0) {        // lane 0's bin is t=0
            float bval = 0.0f;
            if (lane < KMIX) {
                float n0 = __fmul_rn(__fsub_rn(-0.9921875f, mk), ivk);
                bval = __fadd_rn(__fsub_rn(n0, xla_softplus(n0)), lpik);
            }
            #pragma unroll
            for (int k = 0; k < KMIX; k++) {
                float v = __shfl_sync(FULLMASK, bval, k);
                if (lane == 0) lp0[k] = v;
            }
        }
        if (lb >= 224) {      // lane (255-lb) has t=255
            const int lane255 = 255 - lb;
            float bval = 0.0f;
            if (lane < KMIX) {
                float n = __fmul_rn(__fsub_rn(0.9921875f, mk), ivk);
                bval = __fadd_rn(-xla_softplus(n), lpik);
            }
            #pragma unroll
            for (int k = 0; k < KMIX; k++) {
                float v = __shfl_sync(FULLMASK, bval, k);
                if (lane == lane255) lp0[k] = v;
            }
        }

        // per-bin logsumexp over k (sequential ascending k; packed sub + exps)
        float bv = -INFINITY;
        int   bt = 0x7FFFFFFF;
        if (v0) {
            float amax = lp0[0];
            #pragma unroll
            for (int k = 1; k < KMIX; k++) amax = fmaxf(amax, lp0[k]);
            ull am2 = pk2(amax, amax);
            float ex[KMIX];
            #pragma unroll
            for (int j = 0; j < KMIX / 2; j++) {
                float da, db;
                up2(add2(pk2(lp0[2 * j], lp0[2 * j + 1]), neg2(am2)), da, db);
                xla_exp2(da, db, ex[2 * j], ex[2 * j + 1]);
            }
            float sum = 0.0f;
            #pragma unroll
            for (int k = 0; k < KMIX; k++) sum = __fadd_rn(sum, ex[k]);
            bv = __fadd_rn(xla_log(sum), amax);
            bt = t0;
        }

        // warp argmax (first-index tie semantics)
        #pragma unroll
        for (int off = 16; off; off >>= 1) {
            float ov = __shfl_down_sync(FULLMASK, bv, off);
            int   ot = __shfl_down_sync(FULLMASK, bt, off);
            if (ov > bv || (ov == bv && ot < bt)) { bv = ov; bt = ot; }
        }

        // extra-bin logsumexp (uniform result; final compare on lane 0)
        if (haveExtra) {
            float amax = lpe;
            #pragma unroll
            for (int off = 16; off; off >>= 1)
                amax = fmaxf(amax, __shfl_xor_sync(FULLMASK, amax, off));
            float e = xla_exp(__fsub_rn(lpe, amax));
            float sum = 0.0f;
            #pragma unroll
            for (int k = 0; k < KMIX; k++)
                sum = __fadd_rn(sum, __shfl_sync(FULLMASK, e, k));
            float val = __fadd_rn(xla_log(sum), amax);
            if (lane == 0 && val > bv) { bv = val; bt = te; }
        }

        bt = __shfl_sync(FULLMASK, bt, 0);

        float outv = __fdiv_rn(__fsub_rn((float)bt, 127.5f), 127.5f);
        if (c == 0) xr = outv;
        else if (c == 1) xg = outv;

        if (lane == 0) {
            out[(size_t)(b * 3 + c) * HW + hw] = outv;
        }
    }
}

extern "C" void kernel_launch(void* const* d_in, const int* in_sizes, int n_in,
                              void* d_out, int out_size)
{
    const float* x   = (const float*)d_in[0];
    const float* l   = (const float*)d_in[1];
    const int*   eps = (const int*)d_in[2];
    float* out = (float*)d_out;

    int npix = in_sizes[0] / 3;
    int blocks = (npix + NWARPS - 1) / NWARPS;
    mixlogistic_decode_kernel<<<blocks, 32 * NWARPS>>>(x, l, eps, out, npix);
}

// round 17
// speedup vs baseline: 1.5161x; 1.0177x over previous
#include <cuda_runtime.h>

// Math replicates XLA:CPU cephes/Eigen lowering bit-for-bit (validated R5-R16).
// f32x2 packed ops do two independent IEEE-rn f32 ops -> bitwise identical per
// half. rcp.rn(x) == div.rn(1,x) bitwise (validated R10+).
// Params via shuffle-broadcast (smem float4 path regressed, R10). NWARPS=8.
// Boundary bins via post-loop warp-uniform fixups (R14). Fallback log fused
// into main log2 (R15). Extra-bin region: 4 exps in 2 packed calls + shared
// log with input select (this round).

#define FULLMASK 0xFFFFFFFFu
#define NWARPS 8
#define KMIX 10
#define HW 1024
#define LOG127_5 4.8481163645984802f

typedef unsigned long long ull;

__device__ __forceinline__ ull pk2(float a, float b) {
    ull r; asm("mov.b64 %0,{%1,%2};" : "=l"(r) : "f"(a), "f"(b)); return r;
}
__device__ __forceinline__ void up2(ull p, float& a, float& b) {
    asm("mov.b64 {%0,%1},%2;" : "=f"(a), "=f"(b) : "l"(p));
}
__device__ __forceinline__ ull mul2(ull a, ull b) {
    ull r; asm("mul.rn.f32x2 %0,%1,%2;" : "=l"(r) : "l"(a), "l"(b)); return r;
}
__device__ __forceinline__ ull add2(ull a, ull b) {
    ull r; asm("add.rn.f32x2 %0,%1,%2;" : "=l"(r) : "l"(a), "l"(b)); return r;
}
__device__ __forceinline__ ull fma2(ull a, ull b, ull c) {
    ull r; asm("fma.rn.f32x2 %0,%1,%2,%3;" : "=l"(r) : "l"(a), "l"(b), "l"(c)); return r;
}
__device__ __forceinline__ ull neg2(ull a) { return a ^ 0x8000000080000000ull; }
__device__ __forceinline__ float rcp_rn(float x) {
    float r; asm("rcp.rn.f32 %0,%1;" : "=f"(r) : "f"(x)); return r;
}

// ---- scalar cephes exp/log (reference-bit-exact) ----
__device__ __forceinline__ float xla_exp(float x) {
    x = fminf(fmaxf(x, -88.3762626647949f), 88.3762626647950f);
    float fx = floorf(__fmaf_rn(x, 1.44269504088896341f, 0.5f));
    float r = __fsub_rn(x, __fmul_rn(fx, 0.693359375f));
    r = __fsub_rn(r, __fmul_rn(fx, -2.12194440e-4f));
    float z = __fmul_rn(r, r);
    float y = 1.9875691500E-4f;
    y = __fmaf_rn(y, r, 1.3981999507E-3f);
    y = __fmaf_rn(y, r, 8.3334519073E-3f);
    y = __fmaf_rn(y, r, 4.1665795894E-2f);
    y = __fmaf_rn(y, r, 1.6666665459E-1f);
    y = __fmaf_rn(y, r, 5.0000001201E-1f);
    y = __fmaf_rn(y, z, r);
    y = __fadd_rn(y, 1.0f);
    int n = (int)fx;
    return __fmul_rn(y, __int_as_float((n + 127) << 23));
}

__device__ __forceinline__ float xla_log(float x) {
    int bits = __float_as_int(x);
    float e = (float)((bits >> 23) - 126);
    float m = __int_as_float((bits & 0x007fffff) | 0x3f000000);
    if (m < 0.707106781186547524f) {
        e = __fsub_rn(e, 1.0f);
        m = __fadd_rn(__fsub_rn(m, 1.0f), m);
    } else {
        m = __fsub_rn(m, 1.0f);
    }
    float z = __fmul_rn(m, m);
    float y = 7.0376836292E-2f;
    y = __fmaf_rn(y, m, -1.1514610310E-1f);
    y = __fmaf_rn(y, m, 1.1676998740E-1f);
    y = __fmaf_rn(y, m, -1.2420140846E-1f);
    y = __fmaf_rn(y, m, 1.4249322787E-1f);
    y = __fmaf_rn(y, m, -1.6668057665E-1f);
    y = __fmaf_rn(y, m, 2.0000714765E-1f);
    y = __fmaf_rn(y, m, -2.4999993993E-1f);
    y = __fmaf_rn(y, m, 3.3333331174E-1f);
    y = __fmul_rn(y, m);
    y = __fmul_rn(y, z);
    y = __fadd_rn(y, __fmul_rn(e, -2.12194440e-4f));
    y = __fsub_rn(y, __fmul_rn(z, 0.5f));
    float res = __fadd_rn(m, y);
    res = __fadd_rn(res, __fmul_rn(e, 0.693359375f));
    return res;
}

// ---- packed-pair exp/log: bitwise identical per half to scalar versions ----
__device__ __forceinline__ void xla_exp2(float xa, float xb, float& ra, float& rb) {
    xa = fminf(fmaxf(xa, -88.3762626647949f), 88.3762626647950f);
    xb = fminf(fmaxf(xb, -88.3762626647949f), 88.3762626647950f);
    ull x2 = pk2(xa, xb);
    ull fx2 = fma2(x2, pk2(1.44269504088896341f, 1.44269504088896341f),
                   pk2(0.5f, 0.5f));
    float fa, fb; up2(fx2, fa, fb);
    fa = floorf(fa); fb = floorf(fb);
    fx2 = pk2(fa, fb);
    ull r2 = add2(x2, neg2(mul2(fx2, pk2(0.693359375f, 0.693359375f))));
    r2 = add2(r2, neg2(mul2(fx2, pk2(-2.12194440e-4f, -2.12194440e-4f))));
    ull z2 = mul2(r2, r2);
    ull y2 = pk2(1.9875691500E-4f, 1.9875691500E-4f);
    y2 = fma2(y2, r2, pk2(1.3981999507E-3f, 1.3981999507E-3f));
    y2 = fma2(y2, r2, pk2(8.3334519073E-3f, 8.3334519073E-3f));
    y2 = fma2(y2, r2, pk2(4.1665795894E-2f, 4.1665795894E-2f));
    y2 = fma2(y2, r2, pk2(1.6666665459E-1f, 1.6666665459E-1f));
    y2 = fma2(y2, r2, pk2(5.0000001201E-1f, 5.0000001201E-1f));
    y2 = fma2(y2, z2, r2);
    y2 = add2(y2, pk2(1.0f, 1.0f));
    float ya, yb; up2(y2, ya, yb);
    int na = (int)fa, nb = (int)fb;
    ra = __fmul_rn(ya, __int_as_float((na + 127) << 23));
    rb = __fmul_rn(yb, __int_as_float((nb + 127) << 23));
}

__device__ __forceinline__ void xla_log2(float xa, float xb, float& ra, float& rb) {
    int ba = __float_as_int(xa), bb = __float_as_int(xb);
    float ea = (float)((ba >> 23) - 126);
    float eb = (float)((bb >> 23) - 126);
    float ma = __int_as_float((ba & 0x007fffff) | 0x3f000000);
    float mb = __int_as_float((bb & 0x007fffff) | 0x3f000000);
    if (ma < 0.707106781186547524f) {
        ea = __fsub_rn(ea, 1.0f);
        ma = __fadd_rn(__fsub_rn(ma, 1.0f), ma);
    } else {
        ma = __fsub_rn(ma, 1.0f);
    }
    if (mb < 0.707106781186547524f) {
        eb = __fsub_rn(eb, 1.0f);
        mb = __fadd_rn(__fsub_rn(mb, 1.0f), mb);
    } else {
        mb = __fsub_rn(mb, 1.0f);
    }
    ull m2 = pk2(ma, mb);
    ull z2 = mul2(m2, m2);
    ull y2 = pk2(7.0376836292E-2f, 7.0376836292E-2f);
    y2 = fma2(y2, m2, pk2(-1.1514610310E-1f, -1.1514610310E-1f));
    y2 = fma2(y2, m2, pk2(1.1676998740E-1f, 1.1676998740E-1f));
    y2 = fma2(y2, m2, pk2(-1.2420140846E-1f, -1.2420140846E-1f));
    y2 = fma2(y2, m2, pk2(1.4249322787E-1f, 1.4249322787E-1f));
    y2 = fma2(y2, m2, pk2(-1.6668057665E-1f, -1.6668057665E-1f));
    y2 = fma2(y2, m2, pk2(2.0000714765E-1f, 2.0000714765E-1f));
    y2 = fma2(y2, m2, pk2(-2.4999993993E-1f, -2.4999993993E-1f));
    y2 = fma2(y2, m2, pk2(3.3333331174E-1f, 3.3333331174E-1f));
    y2 = mul2(y2, m2);
    y2 = mul2(y2, z2);
    ull e2 = pk2(ea, eb);
    y2 = add2(y2, mul2(e2, pk2(-2.12194440e-4f, -2.12194440e-4f)));
    y2 = add2(y2, neg2(mul2(z2, pk2(0.5f, 0.5f))));
    ull res2 = add2(m2, y2);
    res2 = add2(res2, mul2(e2, pk2(0.693359375f, 0.693359375f)));
    up2(res2, ra, rb);
}

__device__ __forceinline__ float xla_log1p(float x) {
    float u = __fadd_rn(x, 1.0f);
    float w = __fmul_rn(xla_log(u), __fdiv_rn(x, __fsub_rn(u, 1.0f)));
    return (u == 1.0f) ? x : w;
}

__device__ __forceinline__ float xla_tanh(float x) {
    float xc = fminf(fmaxf(x, -7.90531110763549805f), 7.90531110763549805f);
    float x2 = __fmul_rn(xc, xc);
    float p = -2.76076847742355e-16f;
    p = __fmaf_rn(p, x2, 2.00018790482477e-13f);
    p = __fmaf_rn(p, x2, -8.60467152213735e-11f);
    p = __fmaf_rn(p, x2, 5.12229709037114e-08f);
    p = __fmaf_rn(p, x2, 1.48572235717979e-05f);
    p = __fmaf_rn(p, x2, 6.37261928875436e-04f);
    p = __fmaf_rn(p, x2, 4.89352455891786e-03f);
    float num = __fmul_rn(xc, p);
    float q = 1.19825839466702e-06f;
    q = __fmaf_rn(q, x2, 1.18534705686654e-04f);
    q = __fmaf_rn(q, x2, 2.26843463243900e-03f);
    q = __fmaf_rn(q, x2, 4.89352518554385e-03f);
    float r = __fdiv_rn(num, q);
    return (fabsf(x) < 0.0004f) ? x : r;
}

__device__ __forceinline__ float xla_softplus(float x) {
    return __fadd_rn(fmaxf(x, 0.0f), xla_log1p(xla_exp(-fabsf(x))));
}

__global__ __launch_bounds__(32 * NWARPS)
void mixlogistic_decode_kernel(const float* __restrict__ x,
                               const float* __restrict__ l,
                               const int* __restrict__ epsp,
                               float* __restrict__ out,
                               int npix)
{
    __shared__ float sLOG[NWARPS][KMIX];
    __shared__ float sLPI[NWARPS][KMIX];
    __shared__ float sM  [NWARPS][3][KMIX];
    __shared__ float sS  [NWARPS][3][KMIX];
    __shared__ float sINV[NWARPS][3][KMIX];
    __shared__ float sCF [NWARPS][3][KMIX];

    const int warp = threadIdx.x >> 5;
    const int lane = threadIdx.x & 31;
    const int P = blockIdx.x * NWARPS + warp;
    if (P >= npix) return;

    const int b  = P >> 10;
    const int hw = P & (HW - 1);

    for (int c = lane; c < 100; c += 32) {
        float v = l[(size_t)(b * 100 + c) * HW + hw];
        if (c < KMIX) {
            sLOG[warp][c] = v;
        } else {
            int cc  = (c - KMIX) / 30;
            int rem = (c - KMIX) % 30;
            int grp = rem / KMIX;
            int k   = rem % KMIX;
            if (grp == 0) {
                sM[warp][cc][k] = v;
            } else if (grp == 1) {
                float s = fmaxf(v, -7.0f);
                sS[warp][cc][k]   = s;
                sINV[warp][cc][k] = xla_exp(-s);
            } else {
                sCF[warp][cc][k] = xla_tanh(v);
            }
        }
    }
    __syncwarp();

    // cooperative log_softmax (exact fmax butterfly + parallel exp +
    // sequential ascending-k fold == XLA reduce rounding)
    {
        float lg = (lane < KMIX) ? sLOG[warp][lane] : -INFINITY;
        float mx = lg;
        #pragma unroll
        for (int off = 16; off; off >>= 1)
            mx = fmaxf(mx, __shfl_xor_sync(FULLMASK, mx, off));
        float e = xla_exp(__fsub_rn(lg, mx));
        float sum = 0.0f;
        #pragma unroll
        for (int k = 0; k < KMIX; k++)
            sum = __fadd_rn(sum, __shfl_sync(FULLMASK, e, k));
        float lsum = xla_log(sum);
        if (lane < KMIX)
            sLPI[warp][lane] = __fsub_rn(__fsub_rn(lg, mx), lsum);
    }
    __syncwarp();

    const int eps = epsp[0];
    float xr = 0.0f, xg = 0.0f;

    #pragma unroll
    for (int c = 0; c < 3; c++) {
        float xorig = x[(size_t)(b * 3 + c) * HW + hw];
        int r  = (int)(__fadd_rn(__fmul_rn(xorig, 127.5f), 127.5f));
        int lb = max(r - eps, 0);
        int ub = min(r + eps, 255);

        const int t0 = lb + lane;
        const bool v0 = (t0 <= ub);
        const float chi = __fadd_rn(__fmul_rn((float)(t0 + 1), 0.0078125f), -1.0f);

        const int te = lb + 32;
        const bool haveExtra = (te <= ub);

        // per-component params + boundary/extra-bin work, lanes 0..9
        float mk = 0.0f, ivk = 0.0f, sk = 0.0f, lpik = 0.0f;
        float E = 0.0f, lpe = -INFINITY;
        if (lane < KMIX) {
            mk = sM[warp][c][lane];
            if (c == 1) {
                mk = __fadd_rn(mk, __fmul_rn(sCF[warp][0][lane], xr));
            } else if (c == 2) {
                mk = __fadd_rn(mk, __fmul_rn(sCF[warp][1][lane], xr));
                mk = __fadd_rn(mk, __fmul_rn(sCF[warp][2][lane], xg));
            }
            ivk  = sINV[warp][c][lane];
            sk   = sS[warp][c][lane];
            lpik = sLPI[warp][lane];

            // 4 exps in 2 packed calls: (zE, zLo) and (zHi, -|mid|).
            // E = sigmoid at colors[lb] (lb==0 case overwritten by fixup).
            float cE  = __fadd_rn(__fmul_rn((float)lb, 0.0078125f), -1.0f);
            float cLo = __fadd_rn(__fmul_rn((float)te, 0.0078125f), -1.0f);
            float cHi = __fadd_rn(__fmul_rn((float)(te + 1), 0.0078125f), -1.0f);
            float mc  = __fadd_rn(__fmul_rn((float)(2 * te + 1), 0.00390625f), -1.0f);
            float zE  = __fmul_rn(__fsub_rn(cE,  mk), ivk);
            float zLo = __fmul_rn(__fsub_rn(cLo, mk), ivk);
            float zHi = __fmul_rn(__fsub_rn(cHi, mk), ivk);
            float mid = __fmul_rn(__fsub_rn(mc,  mk), ivk);
            float eE, eLo, eHi, eM;
            xla_exp2(-zE, -zLo, eE, eLo);
            xla_exp2(-zHi, -fabsf(mid), eHi, eM);
            E = rcp_rn(__fadd_rn(1.0f, eE));

            if (haveExtra) {            // warp-uniform within lane<KMIX region
                if (te == 255) {        // rare (lb==223): exact -softplus path
                    lpe = __fadd_rn(-xla_softplus(zLo), lpik);
                } else {
                    float shi = rcp_rn(__fadd_rn(1.0f, eHi));
                    float slo = rcp_rn(__fadd_rn(1.0f, eLo));
                    float pdf = __fsub_rn(shi, slo);
                    bool f = !(pdf > 1e-5f);
                    float u = __fadd_rn(eM, 1.0f);
                    float lin = f ? u : fmaxf(pdf, 1e-12f);
                    float L = xla_log(lin);      // shared log (interior or log1p)
                    float core = L;
                    if (f) {
                        float w  = __fmul_rn(L, __fdiv_rn(eM, __fsub_rn(u, 1.0f)));
                        float l1 = (u == 1.0f) ? eM : w;
                        float sp = __fadd_rn(fmaxf(mid, 0.0f), l1);
                        core = __fsub_rn(__fsub_rn(__fsub_rn(mid, sk),
                                         __fmul_rn(2.0f, sp)), LOG127_5);
                    }
                    lpe = __fadd_rn(core, lpik);
                }
            }
        }

        // ---- main 32 bins: interior formula for ALL lanes; fallback log fused
        //      into the main log2 via per-half input selection ----
        const float midc = __fadd_rn(__fmul_rn((float)(2 * t0 + 1), 0.00390625f), -1.0f);
        float lp0[KMIX];
        #pragma unroll
        for (int j = 0; j < KMIX / 2; j++) {
            const int k0 = 2 * j, k1 = 2 * j + 1;
            float m0   = __shfl_sync(FULLMASK, mk,   k0);
            float m1   = __shfl_sync(FULLMASK, mk,   k1);
            float iv0  = __shfl_sync(FULLMASK, ivk,  k0);
            float iv1  = __shfl_sync(FULLMASK, ivk,  k1);
            float lpi0 = __shfl_sync(FULLMASK, lpik, k0);
            float lpi1 = __shfl_sync(FULLMASK, lpik, k1);
            float E0   = __shfl_sync(FULLMASK, E,    k0);
            float E1   = __shfl_sync(FULLMASK, E,    k1);

            float zhi0 = __fmul_rn(__fsub_rn(chi, m0), iv0);
            float zhi1 = __fmul_rn(__fsub_rn(chi, m1), iv1);
            float e0, e1;
            xla_exp2(-zhi0, -zhi1, e0, e1);
            float S0 = rcp_rn(__fadd_rn(1.0f, e0));
            float S1 = rcp_rn(__fadd_rn(1.0f, e1));
            float slo0 = __shfl_up_sync(FULLMASK, S0, 1);
            float slo1 = __shfl_up_sync(FULLMASK, S1, 1);
            if (lane == 0) { slo0 = E0; slo1 = E1; }

            float pdf0 = __fsub_rn(S0, slo0);
            float pdf1 = __fsub_rn(S1, slo1);
            bool f0 = !(pdf0 > 1e-5f);
            bool f1 = !(pdf1 > 1e-5f);

            unsigned bal = __ballot_sync(FULLMASK, f0 || f1);
            float lin0 = fmaxf(pdf0, 1e-12f);
            float lin1 = fmaxf(pdf1, 1e-12f);
            float mid0 = 0.0f, mid1 = 0.0f, es0 = 0.0f, es1 = 0.0f;
            float u0 = 0.0f, u1 = 0.0f, s0 = 0.0f, s1 = 0.0f;
            if (bal) {
                s0 = __shfl_sync(FULLMASK, sk, k0);
                s1 = __shfl_sync(FULLMASK, sk, k1);
                mid0 = __fmul_rn(__fsub_rn(midc, m0), iv0);
                mid1 = __fmul_rn(__fsub_rn(midc, m1), iv1);
                xla_exp2(-fabsf(mid0), -fabsf(mid1), es0, es1);
                u0 = __fadd_rn(es0, 1.0f);
                u1 = __fadd_rn(es1, 1.0f);
                if (f0) lin0 = u0;
                if (f1) lin1 = u1;
            }

            float L0, L1;
            xla_log2(lin0, lin1, L0, L1);   // one log serves both purposes

            float lpA = L0;
            float lpB = L1;
            if (bal) {
                if (f0) {
                    float w  = __fmul_rn(L0, __fdiv_rn(es0, __fsub_rn(u0, 1.0f)));
                    float l1 = (u0 == 1.0f) ? es0 : w;
                    float sp = __fadd_rn(fmaxf(mid0, 0.0f), l1);
                    lpA = __fsub_rn(__fsub_rn(__fsub_rn(mid0, s0),
                                              __fmul_rn(2.0f, sp)), LOG127_5);
                }
                if (f1) {
                    float w  = __fmul_rn(L1, __fdiv_rn(es1, __fsub_rn(u1, 1.0f)));
                    float l1 = (u1 == 1.0f) ? es1 : w;
                    float sp = __fadd_rn(fmaxf(mid1, 0.0f), l1);
                    lpB = __fsub_rn(__fsub_rn(__fsub_rn(mid1, s1),
                                              __fmul_rn(2.0f, sp)), LOG127_5);
                }
            }
            lp0[k0] = __fadd_rn(lpA, lpi0);
            lp0[k1] = __fadd_rn(lpB, lpi1);
        }

        // ---- boundary fixups (warp-uniform; lanes 0..9 compute exact
        //      reference values per component, affected lane gathers) ----
        if (lb == 0) {        // lane 0's bin is t=0
            float bval = 0.0f;
            if (lane < KMIX) {
                float n0 = __fmul_rn(__fsub_rn(-0.9921875f, mk), ivk);
                bval = __fadd_rn(__fsub_rn(n0, xla_softplus(n0)), lpik);
            }
            #pragma unroll
            for (int k = 0; k < KMIX; k++) {
                float v = __shfl_sync(FULLMASK, bval, k);
                if (lane == 0) lp0[k] = v;
            }
        }
        if (lb >= 224) {      // lane (255-lb) has t=255
            const int lane255 = 255 - lb;
            float bval = 0.0f;
            if (lane < KMIX) {
                float n = __fmul_rn(__fsub_rn(0.9921875f, mk), ivk);
                bval = __fadd_rn(-xla_softplus(n), lpik);
            }
            #pragma unroll
            for (int k = 0; k < KMIX; k++) {
                float v = __shfl_sync(FULLMASK, bval, k);
                if (lane == lane255) lp0[k] = v;
            }
        }

        // per-bin logsumexp over k (sequential ascending k; packed sub + exps)
        float bv = -INFINITY;
        int   bt = 0x7FFFFFFF;
        if (v0) {
            float amax = lp0[0];
            #pragma unroll
            for (int k = 1; k < KMIX; k++) amax = fmaxf(amax, lp0[k]);
            ull am2 = pk2(amax, amax);
            float ex[KMIX];
            #pragma unroll
            for (int j = 0; j < KMIX / 2; j++) {
                float da, db;
                up2(add2(pk2(lp0[2 * j], lp0[2 * j + 1]), neg2(am2)), da, db);
                xla_exp2(da, db, ex[2 * j], ex[2 * j + 1]);
            }
            float sum = 0.0f;
            #pragma unroll
            for (int k = 0; k < KMIX; k++) sum = __fadd_rn(sum, ex[k]);
            bv = __fadd_rn(xla_log(sum), amax);
            bt = t0;
        }

        // warp argmax (first-index tie semantics)
        #pragma unroll
        for (int off = 16; off; off >>= 1) {
            float ov = __shfl_down_sync(FULLMASK, bv, off);
            int   ot = __shfl_down_sync(FULLMASK, bt, off);
            if (ov > bv || (ov == bv && ot < bt)) { bv = ov; bt = ot; }
        }

        // extra-bin logsumexp (uniform result; final compare on lane 0)
        if (haveExtra) {
            float amax = lpe;
            #pragma unroll
            for (int off = 16; off; off >>= 1)
                amax = fmaxf(amax, __shfl_xor_sync(FULLMASK, amax, off));
            float e = xla_exp(__fsub_rn(lpe, amax));
            float sum = 0.0f;
            #pragma unroll
            for (int k = 0; k < KMIX; k++)
                sum = __fadd_rn(sum, __shfl_sync(FULLMASK, e, k));
            float val = __fadd_rn(xla_log(sum), amax);
            if (lane == 0 && val > bv) { bv = val; bt = te; }
        }

        bt = __shfl_sync(FULLMASK, bt, 0);

        float outv = __fdiv_rn(__fsub_rn((float)bt, 127.5f), 127.5f);
        if (c == 0) xr = outv;
        else if (c == 1) xg = outv;

        if (lane == 0) {
            out[(size_t)(b * 3 + c) * HW + hw] = outv;
        }
    }
}

extern "C" void kernel_launch(void* const* d_in, const int* in_sizes, int n_in,
                              void* d_out, int out_size)
{
    const float* x   = (const float*)d_in[0];
    const float* l   = (const float*)d_in[1];
    const int*   eps = (const int*)d_in[2];
    float* out = (float*)d_out;

    int npix = in_sizes[0] / 3;
    int blocks = (npix + NWARPS - 1) / NWARPS;
    mixlogistic_decode_kernel<<<blocks, 32 * NWARPS>>>(x, l, eps, out, npix);
}